// round 6
// baseline (speedup 1.0000x reference)
#include <cuda_runtime.h>

#define BB 2
#define HH 128
#define WW 128
#define CC 128
#define NBR 9
#define TILE_P 16
#define NEDGE (TILE_P*NBR)   /* 144 */
#define NTHREADS 256

// ---------------- device scratch (no cudaMalloc allowed) ----------------
__device__ float g_norm[BB*HH*WW*CC];              // 16 MB LN1 output
__device__ float g_Ud[CC*CC], g_Vd[CC*CC];         // folded drive-MLP weights
__device__ float g_Ur[CC*CC], g_Vr[CC*CC];         // folded res-MLP weights
__device__ float g_biasd[NBR*CC], g_biasr[NBR*CC]; // per-neighbor bias (rel_pos folded)

// ---------------- helpers ----------------
__device__ __forceinline__ float2 ffma2(float2 a, float2 b, float2 c) {
    unsigned long long au = *reinterpret_cast<unsigned long long*>(&a);
    unsigned long long bu = *reinterpret_cast<unsigned long long*>(&b);
    unsigned long long cu = *reinterpret_cast<unsigned long long*>(&c);
    unsigned long long du;
    asm("fma.rn.f32x2 %0, %1, %2, %3;" : "=l"(du) : "l"(au), "l"(bu), "l"(cu));
    return *reinterpret_cast<float2*>(&du);
}

__device__ __forceinline__ float gelu_exact(float x) {
    return 0.5f * x * (1.0f + erff(x * 0.70710678118654752f));
}

// ---------------- setup: prep (fold weights) + LN1, merged ----------------
__global__ void setup_kernel(const float* __restrict__ tokens,
                             const float* __restrict__ g, const float* __restrict__ b,
                             const float* __restrict__ dW1, const float* __restrict__ db1,
                             const float* __restrict__ rW1, const float* __restrict__ rb1,
                             const float* __restrict__ rel_pos) {
    if (blockIdx.x < 4096) {
        // --- LN1: 8 rows per block ---
        int warp = threadIdx.x >> 5, lane = threadIdx.x & 31;
        int row  = blockIdx.x * 8 + warp;
        float4 x = reinterpret_cast<const float4*>(tokens + (long)row*CC)[lane];
        float s = x.x + x.y + x.z + x.w;
        #pragma unroll
        for (int o = 16; o; o >>= 1) s += __shfl_xor_sync(0xffffffffu, s, o);
        float m = s * (1.0f/128.0f);
        float dx = x.x - m, dy = x.y - m, dz = x.z - m, dw = x.w - m;
        float v = dx*dx + dy*dy + dz*dz + dw*dw;
        #pragma unroll
        for (int o = 16; o; o >>= 1) v += __shfl_xor_sync(0xffffffffu, v, o);
        float rs = rsqrtf(v * (1.0f/128.0f) + 1e-5f);
        int c = lane * 4;
        float4 o4;
        o4.x = dx*rs*g[c+0] + b[c+0];
        o4.y = dy*rs*g[c+1] + b[c+1];
        o4.z = dz*rs*g[c+2] + b[c+2];
        o4.w = dw*rs*g[c+3] + b[c+3];
        reinterpret_cast<float4*>(g_norm + (long)row*CC)[lane] = o4;
    } else {
        // --- prep: fold dW1/rW1 + rel_pos into U/V/bias ---
        int idx = (blockIdx.x - 4096) * blockDim.x + threadIdx.x;
        if (idx < CC*CC) {
            int c = idx >> 7, j = idx & 127;
            g_Ud[idx] = dW1[c*CC + j]       + dW1[(256 + c)*CC + j];
            g_Vd[idx] = dW1[(128 + c)*CC+j] - dW1[(256 + c)*CC + j];
            g_Ur[idx] = rW1[c*CC + j]       + rW1[(256 + c)*CC + j];
            g_Vr[idx] = rW1[(128 + c)*CC+j] - rW1[(256 + c)*CC + j];
        }
        if (idx < NBR*CC) {
            int n = idx >> 7, j = idx & 127;
            float bd = db1[j], br = rb1[j];
            #pragma unroll
            for (int r = 0; r < 8; ++r) {
                float rp = rel_pos[n*8 + r];
                bd += rp * dW1[(384 + r)*CC + j];
                br += rp * rW1[(384 + r)*CC + j];
            }
            g_biasd[idx] = bd;
            g_biasr[idx] = br;
        }
    }
}

// ---------------- fused main kernel: one CTA = 16 positions ----------------
__global__ __launch_bounds__(NTHREADS, 2)
void eml_main_kernel(const float* __restrict__ tokens,
                     const float* __restrict__ ln2_g, const float* __restrict__ ln2_b,
                     const float* __restrict__ dW2, const float* __restrict__ db2,
                     const float* __restrict__ rW2, const float* __restrict__ rb2,
                     const float* __restrict__ vW,  const float* __restrict__ vb,
                     const float* __restrict__ oW,  const float* __restrict__ ob,
                     const float* __restrict__ p_gamma, const float* __restrict__ p_lam,
                     const float* __restrict__ p_bias,
                     float* __restrict__ out) {
    extern __shared__ float sm[];
    float* nbS    = sm;                       // [144][128] scrambled nbhd tile
    float* cuS    = nbS    + NEDGE*CC;        // [16][256] center@(Ud|Ur)
    float* biasS  = cuS    + TILE_P*256;      // [9][256]
    float* cenS   = biasS  + NBR*256;         // [16][128] centers (reused as wsS)
    float* driveS = cenS   + TILE_P*CC;       // [144]
    float* resS   = driveS + NEDGE;           // [144]
    float* gateS  = resS   + NEDGE;           // [144]
    float* invmS  = gateS  + NEDGE;           // [16]
    float* sgS    = invmS  + TILE_P;          // [16]
    float* wsS  = cenS;    // reuse (cen dead after cu phase)
    float* msgS = cuS;     // reuse (cu dead after GEMM)
    float* uS   = nbS;     // reuse (nb dead after weighted sum)

    const int tid = threadIdx.x;
    const int blk = blockIdx.x;
    const int b   = blk >> 10;
    const int t   = blk & 1023;
    const int h   = t >> 3;
    const int w0  = (t & 7) << 4;
    const int rowbase = (b*HH + h)*WW + w0;   // flat position index of p=0
    const int lane = tid & 31;

    // --- stage bias table [9][256] ---
    for (int idx = tid; idx < NBR*256; idx += NTHREADS) {
        int n = idx >> 8, j = idx & 255;
        biasS[idx] = (j < 128) ? g_biasd[n*CC + j] : g_biasr[n*CC + j - 128];
    }
    // --- stage centers [16][128] ---
    for (int idx = tid; idx < TILE_P*CC; idx += NTHREADS)
        cenS[idx] = g_norm[(long)rowbase*CC + idx];
    // --- gather scrambled nbhd, SOURCE-MAJOR iteration for coalesced loads ---
    // nbhd[p,n,c] = padnorm[shift s][c2] with f = n*128+c = c2*9+s.
    // Iterate idx = (p, s, c2): loads are contiguous c2 runs; stores stride-9 (bank-free).
    for (int idx = tid; idx < TILE_P*NBR*CC; idx += NTHREADS) {
        int p  = idx / 1152;              // 1152 = 9*128
        int r  = idx - p*1152;
        int s  = r >> 7;                  // shift index 0..8
        int c2 = r & 127;                 // source channel
        int f  = c2*9 + s;
        int n  = f >> 7;
        int c  = f & 127;
        int di = s / 3;
        int dj = s - di*3;
        int hh = h + di - 1;
        int ww = w0 + p + dj - 1;
        float val = 0.0f;
        if ((unsigned)hh < HH && (unsigned)ww < WW)
            val = g_norm[(((long)(b*HH + hh)*WW + ww))*CC + c2];
        nbS[(p*9 + n)*CC + c] = val;
    }
    __syncthreads();

    // --- cu = center @ [Ud|Ur]: warp = 32-j block, thread accumulates all 16 p ---
    {
        const int wj = (tid >> 5) << 5;             // warp's j base (0..224)
        const int j  = wj + lane;                   // 0..255
        const float* Up = (j < 128) ? (g_Ud + j) : (g_Ur + j - 128);
        float acc[TILE_P];
        #pragma unroll
        for (int p = 0; p < TILE_P; ++p) acc[p] = 0.0f;
        for (int c0 = 0; c0 < CC; c0 += 4) {
            float4 cq[TILE_P];
            #pragma unroll
            for (int p = 0; p < TILE_P; ++p)
                cq[p] = *reinterpret_cast<const float4*>(cenS + p*CC + c0);
            #pragma unroll
            for (int cc = 0; cc < 4; ++cc) {
                float u = Up[(c0 + cc)*CC];         // coalesced 128B per warp
                #pragma unroll
                for (int p = 0; p < TILE_P; ++p) {
                    float cv = (cc == 0) ? cq[p].x : (cc == 1) ? cq[p].y
                             : (cc == 2) ? cq[p].z : cq[p].w;
                    acc[p] = fmaf(cv, u, acc[p]);
                }
            }
        }
        #pragma unroll
        for (int p = 0; p < TILE_P; ++p)
            cuS[p*256 + j] = acc[p];
    }
    __syncthreads();

    // --- edge GEMM: thread (ty,tx) = position ty, j-octet tx; 2 passes (drive/res) ---
    {
        const int ty = tid >> 4;                   // position 0..15
        const int tx = tid & 15;                   // j-octet 0..15
        const float* nbp = nbS + ty*9*CC;
        #pragma unroll
        for (int pass = 0; pass < 2; ++pass) {
            const float* Vp  = ((pass == 0) ? g_Vd : g_Vr) + tx*8;
            const float* W2p = ((pass == 0) ? dW2  : rW2)  + tx*8;
            float w2[8];
            #pragma unroll
            for (int q = 0; q < 8; ++q) w2[q] = W2p[q];

            float2 acc[9][4];
            {
                const float* cub = cuS + ty*256 + pass*128 + tx*8;
                float4 cu0 = *reinterpret_cast<const float4*>(cub);
                float4 cu1 = *reinterpret_cast<const float4*>(cub + 4);
                #pragma unroll
                for (int i = 0; i < 9; ++i) {
                    const float* bb = biasS + i*256 + pass*128 + tx*8;
                    float4 b0 = *reinterpret_cast<const float4*>(bb);
                    float4 b1 = *reinterpret_cast<const float4*>(bb + 4);
                    acc[i][0] = make_float2(cu0.x + b0.x, cu0.y + b0.y);
                    acc[i][1] = make_float2(cu0.z + b0.z, cu0.w + b0.w);
                    acc[i][2] = make_float2(cu1.x + b1.x, cu1.y + b1.y);
                    acc[i][3] = make_float2(cu1.z + b1.z, cu1.w + b1.w);
                }
            }
            #pragma unroll 2
            for (int c0 = 0; c0 < CC; c0 += 2) {
                float2 nbq[9];
                #pragma unroll
                for (int i = 0; i < 9; ++i)
                    nbq[i] = *reinterpret_cast<const float2*>(nbp + i*CC + c0);
                #pragma unroll
                for (int cc = 0; cc < 2; ++cc) {
                    const float* vr = Vp + (c0 + cc)*CC;
                    float4 v0 = *reinterpret_cast<const float4*>(vr);
                    float4 v1 = *reinterpret_cast<const float4*>(vr + 4);
                    float2 vA = make_float2(v0.x, v0.y);
                    float2 vB = make_float2(v0.z, v0.w);
                    float2 vC = make_float2(v1.x, v1.y);
                    float2 vD = make_float2(v1.z, v1.w);
                    #pragma unroll
                    for (int i = 0; i < 9; ++i) {
                        float nbv = cc ? nbq[i].y : nbq[i].x;
                        float2 nb2 = make_float2(nbv, nbv);
                        acc[i][0] = ffma2(nb2, vA, acc[i][0]);
                        acc[i][1] = ffma2(nb2, vB, acc[i][1]);
                        acc[i][2] = ffma2(nb2, vC, acc[i][2]);
                        acc[i][3] = ffma2(nb2, vD, acc[i][3]);
                    }
                }
            }
            #pragma unroll
            for (int i = 0; i < 9; ++i) {
                float s = gelu_exact(acc[i][0].x)*w2[0] + gelu_exact(acc[i][0].y)*w2[1]
                        + gelu_exact(acc[i][1].x)*w2[2] + gelu_exact(acc[i][1].y)*w2[3]
                        + gelu_exact(acc[i][2].x)*w2[4] + gelu_exact(acc[i][2].y)*w2[5]
                        + gelu_exact(acc[i][3].x)*w2[6] + gelu_exact(acc[i][3].y)*w2[7];
                #pragma unroll
                for (int o = 8; o; o >>= 1)
                    s += __shfl_xor_sync(0xffffffffu, s, o);
                if (tx == 0)
                    ((pass == 0) ? driveS : resS)[ty*9 + i] = s;
            }
        }
    }
    __syncthreads();

    // --- EML gate ---
    const float gamma = *p_gamma, lam = *p_lam, ebias = *p_bias;
    if (tid < NEDGE) {
        float d = driveS[tid] + db2[0];
        float r = resS[tid]   + rb2[0];
        float sp = fmaxf(r, 0.0f) + log1pf(expf(-fabsf(r)));   // jax softplus
        float en = gamma * d / (lam * sp + 1e-6f) + ebias;
        en = fminf(fmaxf(en, -3.0f), 3.0f);
        gateS[tid] = 1.0f / (1.0f + expf(-en));
    }
    __syncthreads();
    if (tid < TILE_P) {
        float s = 0.0f;
        #pragma unroll
        for (int n = 0; n < 9; ++n) s += gateS[tid*9 + n];
        sgS[tid]   = s;
        invmS[tid] = 1.0f / fmaxf(s, 1e-6f);
    }
    __syncthreads();

    // --- ws[p][c] = (sum_n gate*nbhd)/mass ---
    {
        int p = tid >> 4, cg = tid & 15;
        float im = invmS[p];
        float gr[9];
        #pragma unroll
        for (int n = 0; n < 9; ++n) gr[n] = gateS[p*9 + n];
        #pragma unroll
        for (int k = 0; k < 8; ++k) {
            int c = cg + (k << 4);
            float s = 0.0f;
            #pragma unroll
            for (int n = 0; n < 9; ++n) s += gr[n] * nbS[(p*9 + n)*CC + c];
            wsS[p*CC + c] = s * im;
        }
    }
    __syncthreads();

    // --- message = ws @ vW + vb*(sum_gate/mass)   (c-outer, contiguous d, packed) ---
    {
        int p = tid >> 4, dg = tid & 15;
        int d0 = dg * 8;                        // thread owns d in [d0, d0+8)
        float coef = sgS[p] * invmS[p];
        float2 acc[4] = {{0,0},{0,0},{0,0},{0,0}};
        const float* wsp = wsS + p*CC;
        #pragma unroll 4
        for (int c = 0; c < CC; ++c) {
            float w = wsp[c];                   // broadcast LDS
            float2 w2 = make_float2(w, w);
            const float4* vr = reinterpret_cast<const float4*>(vW + c*CC + d0);
            float4 v0 = vr[0], v1 = vr[1];
            acc[0] = ffma2(w2, make_float2(v0.x, v0.y), acc[0]);
            acc[1] = ffma2(w2, make_float2(v0.z, v0.w), acc[1]);
            acc[2] = ffma2(w2, make_float2(v1.x, v1.y), acc[2]);
            acc[3] = ffma2(w2, make_float2(v1.z, v1.w), acc[3]);
        }
        #pragma unroll
        for (int k = 0; k < 4; ++k) {
            msgS[p*CC + d0 + 2*k]     = acc[k].x + vb[d0 + 2*k]     * coef;
            msgS[p*CC + d0 + 2*k + 1] = acc[k].y + vb[d0 + 2*k + 1] * coef;
        }
    }
    __syncthreads();

    // --- u = tokens + message @ oW + ob   (same structure) ---
    {
        int p = tid >> 4, dg = tid & 15;
        int d0 = dg * 8;
        long grow = (long)(rowbase + p) * CC;
        float2 acc[4] = {{0,0},{0,0},{0,0},{0,0}};
        const float* mp = msgS + p*CC;
        #pragma unroll 4
        for (int c = 0; c < CC; ++c) {
            float w = mp[c];
            float2 w2 = make_float2(w, w);
            const float4* orr = reinterpret_cast<const float4*>(oW + c*CC + d0);
            float4 v0 = orr[0], v1 = orr[1];
            acc[0] = ffma2(w2, make_float2(v0.x, v0.y), acc[0]);
            acc[1] = ffma2(w2, make_float2(v0.z, v0.w), acc[1]);
            acc[2] = ffma2(w2, make_float2(v1.x, v1.y), acc[2]);
            acc[3] = ffma2(w2, make_float2(v1.z, v1.w), acc[3]);
        }
        __syncthreads();   // msgS reads done before uS (aliases nbS) writes
        #pragma unroll
        for (int k = 0; k < 4; ++k) {
            int d2 = d0 + 2*k;
            uS[p*CC + d2]     = tokens[grow + d2]     + acc[k].x + ob[d2];
            uS[p*CC + d2 + 1] = tokens[grow + d2 + 1] + acc[k].y + ob[d2 + 1];
        }
    }
    __syncthreads();

    // --- LN2 + store ---
    {
        int warp = tid >> 5, lanei = tid & 31;
        #pragma unroll
        for (int pp = 0; pp < 2; ++pp) {
            int p = warp*2 + pp;
            float4 x = reinterpret_cast<const float4*>(uS + p*CC)[lanei];
            float s = x.x + x.y + x.z + x.w;
            #pragma unroll
            for (int o = 16; o; o >>= 1) s += __shfl_xor_sync(0xffffffffu, s, o);
            float m = s * (1.0f/128.0f);
            float dx = x.x - m, dy = x.y - m, dz = x.z - m, dw = x.w - m;
            float v = dx*dx + dy*dy + dz*dz + dw*dw;
            #pragma unroll
            for (int o = 16; o; o >>= 1) v += __shfl_xor_sync(0xffffffffu, v, o);
            float rs = rsqrtf(v * (1.0f/128.0f) + 1e-5f);
            int c = lanei * 4;
            float4 o4;
            o4.x = dx*rs*ln2_g[c+0] + ln2_b[c+0];
            o4.y = dy*rs*ln2_g[c+1] + ln2_b[c+1];
            o4.z = dz*rs*ln2_g[c+2] + ln2_b[c+2];
            o4.w = dw*rs*ln2_g[c+3] + ln2_b[c+3];
            reinterpret_cast<float4*>(out + (long)(rowbase + p)*CC)[lanei] = o4;
        }
    }
}

// ---------------- launch ----------------
extern "C" void kernel_launch(void* const* d_in, const int* in_sizes, int n_in,
                              void* d_out, int out_size) {
    const float* tokens = (const float*)d_in[0];
    const float* ln1_g  = (const float*)d_in[1];
    const float* ln1_b  = (const float*)d_in[2];
    const float* ln2_g  = (const float*)d_in[3];
    const float* ln2_b  = (const float*)d_in[4];
    const float* rel_pos= (const float*)d_in[5];
    const float* dW1    = (const float*)d_in[6];
    const float* db1    = (const float*)d_in[7];
    const float* dW2    = (const float*)d_in[8];
    const float* db2    = (const float*)d_in[9];
    const float* rW1    = (const float*)d_in[10];
    const float* rb1    = (const float*)d_in[11];
    const float* rW2    = (const float*)d_in[12];
    const float* rb2    = (const float*)d_in[13];
    const float* vW     = (const float*)d_in[14];
    const float* vb     = (const float*)d_in[15];
    const float* oW     = (const float*)d_in[16];
    const float* ob     = (const float*)d_in[17];
    const float* gamma  = (const float*)d_in[18];
    const float* lam    = (const float*)d_in[19];
    const float* ebias  = (const float*)d_in[20];
    float* out = (float*)d_out;

    const int SMEM = (NEDGE*CC + TILE_P*256 + NBR*256 + TILE_P*CC + NEDGE*3 + TILE_P*2) * 4;

    setup_kernel<<<4096 + 64, 256>>>(tokens, ln1_g, ln1_b, dW1, db1, rW1, rb1, rel_pos);
    cudaFuncSetAttribute(eml_main_kernel, cudaFuncAttributeMaxDynamicSharedMemorySize, SMEM);
    eml_main_kernel<<<(BB*HH*WW)/TILE_P, 256, SMEM>>>(tokens, ln2_g, ln2_b, dW2, db2,
                                                      rW2, rb2, vW, vb, oW, ob,
                                                      gamma, lam, ebias, out);
}

// round 8
// speedup vs baseline: 1.6640x; 1.6640x over previous
#include <cuda_runtime.h>
#include <cuda_bf16.h>
#include <cstdint>

#define BB 2
#define HH 128
#define WW 128
#define CC 128
#define NBR 9
#define TILE_P 16
#define NEDGE 144
#define NT 512

#define KP 168                 /* padded K cols (336 B rows, ldmatrix conflict-free) */
#define ROWB (KP*2)            /* 336 bytes per row */

// smem byte layout
#define CEN_OFFB  4096                       // [16][128] f32 centers (reused as wsS)
#define A_OFFB    12288                      // A: 144 x 168 bf16 = 48384
#define B_OFFB    (A_OFFB + 48384)           // B: 256 x 168 bf16 = 86016
#define SMEM_TOTAL (B_OFFB + 86016)          // 146688
// misc float indices in smf[0..1023]
#define F_PART  0       /* [144][4] partial j-sums */
#define F_GATE  576
#define F_SG    720
#define F_INVM  736
#define F_W2    768     /* [256]: dW2 | rW2 */

// ---- device scratch ----
__device__ float g_norm[BB*HH*WW*CC];
__device__ float g_Ud[CC*CC], g_Ur[CC*CC];
__device__ unsigned char g_Bimg[256*ROWB];   // static B image (bf16, row-major [j][c])

// ---- helpers ----
__device__ __forceinline__ float gelu_exact(float x) {
    return 0.5f * x * (1.0f + erff(x * 0.70710678118654752f));
}
__device__ __forceinline__ uint32_t smem_u32(const void* p) {
    uint32_t a;
    asm("{ .reg .u64 t; cvta.to.shared.u64 t, %1; cvt.u32.u64 %0, t; }" : "=r"(a) : "l"(p));
    return a;
}
__device__ __forceinline__ void ldm_x4(uint32_t* r, uint32_t addr) {
    asm volatile("ldmatrix.sync.aligned.m8n8.x4.shared.b16 {%0,%1,%2,%3}, [%4];"
        : "=r"(r[0]), "=r"(r[1]), "=r"(r[2]), "=r"(r[3]) : "r"(addr));
}
__device__ __forceinline__ void mma16816(float* c, const uint32_t* a, uint32_t b0, uint32_t b1) {
    asm volatile("mma.sync.aligned.m16n8k16.row.col.f32.bf16.bf16.f32 "
        "{%0,%1,%2,%3}, {%4,%5,%6,%7}, {%8,%9}, {%0,%1,%2,%3};"
        : "+f"(c[0]), "+f"(c[1]), "+f"(c[2]), "+f"(c[3])
        : "r"(a[0]), "r"(a[1]), "r"(a[2]), "r"(a[3]), "r"(b0), "r"(b1));
}

// ================= setup: LN1 + U fold + B image =================
__global__ void setup_kernel(const float* __restrict__ tokens,
                             const float* __restrict__ g, const float* __restrict__ b,
                             const float* __restrict__ dW1, const float* __restrict__ db1,
                             const float* __restrict__ rW1, const float* __restrict__ rb1,
                             const float* __restrict__ rel_pos) {
    if (blockIdx.x < 4096) {
        int warp = threadIdx.x >> 5, lane = threadIdx.x & 31;
        int row  = blockIdx.x * 8 + warp;
        float4 x = reinterpret_cast<const float4*>(tokens + (long)row*CC)[lane];
        float s = x.x + x.y + x.z + x.w;
        #pragma unroll
        for (int o = 16; o; o >>= 1) s += __shfl_xor_sync(0xffffffffu, s, o);
        float m = s * (1.0f/128.0f);
        float dx = x.x - m, dy = x.y - m, dz = x.z - m, dw = x.w - m;
        float v = dx*dx + dy*dy + dz*dz + dw*dw;
        #pragma unroll
        for (int o = 16; o; o >>= 1) v += __shfl_xor_sync(0xffffffffu, v, o);
        float rs = rsqrtf(v * (1.0f/128.0f) + 1e-5f);
        int c = lane * 4;
        float4 o4;
        o4.x = dx*rs*g[c+0] + b[c+0];
        o4.y = dy*rs*g[c+1] + b[c+1];
        o4.z = dz*rs*g[c+2] + b[c+2];
        o4.w = dw*rs*g[c+3] + b[c+3];
        reinterpret_cast<float4*>(g_norm + (long)row*CC)[lane] = o4;
    } else if (blockIdx.x < 4160) {
        int idx = (blockIdx.x - 4096) * 256 + threadIdx.x;   // < 16384
        int c = idx >> 7, j = idx & 127;
        g_Ud[idx] = dW1[c*CC + j] + dW1[(256 + c)*CC + j];
        g_Ur[idx] = rW1[c*CC + j] + rW1[(256 + c)*CC + j];
    } else {
        // B image [256][168] bf16 row-major: cols 0-127 = V fold (transposed),
        // 128-136 = bias rows (rel_pos folded), rest 0 (cu cols filled per-CTA).
        int t = (blockIdx.x - 4160) * 256 + threadIdx.x;     // < 43008
        if (t < 256*KP) {
            int j = t / KP, c = t - (t / KP) * KP;
            float val = 0.0f;
            if (c < 128) {
                val = (j < 128) ? dW1[(128 + c)*CC + j]       - dW1[(256 + c)*CC + j]
                                : rW1[(128 + c)*CC + (j-128)] - rW1[(256 + c)*CC + (j-128)];
            } else if (c < 137) {
                int n = c - 128;
                if (j < 128) {
                    float bd = db1[j];
                    #pragma unroll
                    for (int r = 0; r < 8; ++r) bd += rel_pos[n*8 + r] * dW1[(384 + r)*CC + j];
                    val = bd;
                } else {
                    float br = rb1[j - 128];
                    #pragma unroll
                    for (int r = 0; r < 8; ++r) br += rel_pos[n*8 + r] * rW1[(384 + r)*CC + (j-128)];
                    val = br;
                }
            }
            *(__nv_bfloat16*)(g_Bimg + j*ROWB + c*2) = __float2bfloat16(val);
        }
    }
}

// ================= main fused kernel: CTA = 16 positions =================
__global__ __launch_bounds__(NT, 1)
void eml_main_kernel(const float* __restrict__ tokens,
                     const float* __restrict__ ln2_g, const float* __restrict__ ln2_b,
                     const float* __restrict__ dW2, const float* __restrict__ db2,
                     const float* __restrict__ rW2, const float* __restrict__ rb2,
                     const float* __restrict__ vW,  const float* __restrict__ vb,
                     const float* __restrict__ oW,  const float* __restrict__ ob,
                     const float* __restrict__ p_gamma, const float* __restrict__ p_lam,
                     const float* __restrict__ p_bias,
                     float* __restrict__ out) {
    extern __shared__ char smem[];
    float* smf  = (float*)smem;
    float* cenS = (float*)(smem + CEN_OFFB);      // 16x128 f32, reused as wsS
    float* wsS  = cenS;
    float* msgS = (float*)(smem + A_OFFB);        // reuse A region after ws
    float* uS   = msgS + 2048;
    const uint32_t smb = smem_u32(smem);

    const int tid  = threadIdx.x;
    const int warp = tid >> 5, lane = tid & 31;
    const int blk = blockIdx.x;
    const int b   = blk >> 10;
    const int t   = blk & 1023;
    const int h   = t >> 3;
    const int w0  = (t & 7) << 4;
    const int rowbase = (b*HH + h)*WW + w0;

    // ---- phase 0: zero A, copy B image, stage cen + w2 ----
    {
        uint4 z = make_uint4(0, 0, 0, 0);
        uint4* adst = (uint4*)(smem + A_OFFB);
        #pragma unroll 2
        for (int i = tid; i < 48384/16; i += NT) adst[i] = z;
        const uint4* bsrc = (const uint4*)g_Bimg;
        uint4* bdst = (uint4*)(smem + B_OFFB);
        #pragma unroll 2
        for (int i = tid; i < 86016/16; i += NT) bdst[i] = bsrc[i];
        for (int i = tid; i < TILE_P*CC; i += NT) cenS[i] = g_norm[(long)rowbase*CC + i];
        if (tid < 256) smf[F_W2 + tid] = (tid < 128) ? dW2[tid] : rW2[tid - 128];
    }
    __syncthreads();

    // ---- phase 1: gather scrambled nbhd -> A (bf16); one-hots; cu -> B ext cols ----
    // nbhd[p,n,c] = padnorm[shift s][c2], f = n*128+c = c2*9+s  (source-major)
    for (int idx = tid; idx < TILE_P*NBR*CC; idx += NT) {
        int p  = idx / 1152;
        int r0 = idx - p*1152;
        int s  = r0 >> 7;
        int c2 = r0 & 127;
        int f  = c2*9 + s;
        int n  = f >> 7;
        int c  = f & 127;
        int di = s / 3;
        int dj = s - di*3;
        int hh = h + di - 1;
        int ww = w0 + p + dj - 1;
        float val = 0.0f;
        if ((unsigned)hh < HH && (unsigned)ww < WW)
            val = g_norm[(((long)(b*HH + hh)*WW + ww))*CC + c2];
        int e = p*9 + n;
        *(__nv_bfloat16*)(smem + A_OFFB + e*ROWB + c*2) = __float2bfloat16(val);
    }
    if (tid < NEDGE) {
        int p = tid / 9, n = tid - p*9;
        char* row = smem + A_OFFB + tid*ROWB;
        *(__nv_bfloat16*)(row + (128 + n)*2) = __float2bfloat16(1.0f);
        *(__nv_bfloat16*)(row + (144 + p)*2) = __float2bfloat16(1.0f);
    }
    // cu = center @ [Ud|Ur] (f32 SIMT) -> B[j][144+p] bf16
    {
        const int jj = tid & 255;
        const int ph = tid >> 8;              // 0..1 -> 8 positions each
        const float* Up = (jj < 128) ? (g_Ud + jj) : (g_Ur + jj - 128);
        float acc[8];
        #pragma unroll
        for (int i = 0; i < 8; ++i) acc[i] = 0.0f;
        for (int c0 = 0; c0 < CC; c0 += 4) {
            float4 cq[8];
            #pragma unroll
            for (int i = 0; i < 8; ++i)
                cq[i] = *reinterpret_cast<const float4*>(cenS + (ph*8 + i)*CC + c0);
            #pragma unroll
            for (int cc = 0; cc < 4; ++cc) {
                float u = Up[(c0 + cc)*CC];
                #pragma unroll
                for (int i = 0; i < 8; ++i) {
                    float cv = (cc == 0) ? cq[i].x : (cc == 1) ? cq[i].y
                             : (cc == 2) ? cq[i].z : cq[i].w;
                    acc[i] = fmaf(cv, u, acc[i]);
                }
            }
        }
        #pragma unroll
        for (int i = 0; i < 8; ++i) {
            int p = ph*8 + i;
            *(__nv_bfloat16*)(smem + B_OFFB + jj*ROWB + (144 + p)*2) = __float2bfloat16(acc[i]);
        }
    }
    __syncthreads();

    // ---- phase 2: edge GEMM via mma.sync; 36 tasks = 9 m-tiles x 4 n64-quads ----
    {
        const uint32_t Abase = smb + A_OFFB;
        const uint32_t Bbase = smb + B_OFFB;
        for (int task = warp; task < 36; task += 16) {
            int mt = task % 9;          // m-tile (16 rows)
            int nq = task / 9;          // n64 quad (0,1 = drive; 2,3 = res)
            int m0 = mt * 16;
            // cache A fragments for all 10 k-steps
            uint32_t af[10][4];
            uint32_t aaddr = Abase + (m0 + (lane & 15))*ROWB + ((lane >> 4) << 4);
            #pragma unroll
            for (int k = 0; k < 10; ++k)
                ldm_x4(af[k], aaddr + k*32);
            float part0 = 0.0f, part1 = 0.0f;    // rows m0+lane/4, +8
            const float* w2s = smf + F_W2 + nq*64;
            #pragma unroll
            for (int nb = 0; nb < 4; ++nb) {     // n16 blocks within the quad
                int n0 = nq*64 + nb*16;
                float c0[4] = {0,0,0,0}, c1[4] = {0,0,0,0};
                uint32_t baddr = Bbase + (n0 + (lane & 7) + ((lane >> 4) << 3))*ROWB
                               + (((lane >> 3) & 1) << 4);
                #pragma unroll
                for (int k = 0; k < 10; ++k) {
                    uint32_t bf[4];
                    ldm_x4(bf, baddr + k*32);
                    mma16816(c0, af[k], bf[0], bf[1]);
                    mma16816(c1, af[k], bf[2], bf[3]);
                }
                int jl = nb*16 + (lane & 3)*2;   // local col within 64
                part0 += gelu_exact(c0[0])*w2s[jl]   + gelu_exact(c0[1])*w2s[jl+1]
                       + gelu_exact(c1[0])*w2s[jl+8] + gelu_exact(c1[1])*w2s[jl+9];
                part1 += gelu_exact(c0[2])*w2s[jl]   + gelu_exact(c0[3])*w2s[jl+1]
                       + gelu_exact(c1[2])*w2s[jl+8] + gelu_exact(c1[3])*w2s[jl+9];
            }
            part0 += __shfl_xor_sync(0xffffffffu, part0, 1);
            part0 += __shfl_xor_sync(0xffffffffu, part0, 2);
            part1 += __shfl_xor_sync(0xffffffffu, part1, 1);
            part1 += __shfl_xor_sync(0xffffffffu, part1, 2);
            if ((lane & 3) == 0) {
                int r = m0 + (lane >> 2);
                smf[F_PART + r*4 + nq]       = part0;
                smf[F_PART + (r + 8)*4 + nq] = part1;
            }
        }
    }
    __syncthreads();

    // ---- EML gate ----
    const float gamma = *p_gamma, lam = *p_lam, ebias = *p_bias;
    if (tid < NEDGE) {
        float d = smf[F_PART + tid*4 + 0] + smf[F_PART + tid*4 + 1] + db2[0];
        float r = smf[F_PART + tid*4 + 2] + smf[F_PART + tid*4 + 3] + rb2[0];
        float sp = fmaxf(r, 0.0f) + log1pf(expf(-fabsf(r)));
        float en = gamma * d / (lam * sp + 1e-6f) + ebias;
        en = fminf(fmaxf(en, -3.0f), 3.0f);
        smf[F_GATE + tid] = 1.0f / (1.0f + expf(-en));
    }
    __syncthreads();
    if (tid < TILE_P) {
        float s = 0.0f;
        #pragma unroll
        for (int n = 0; n < 9; ++n) s += smf[F_GATE + tid*9 + n];
        smf[F_SG + tid]   = s;
        smf[F_INVM + tid] = 1.0f / fmaxf(s, 1e-6f);
    }
    __syncthreads();

    // ---- ws[p][c] = (sum_n gate*nbhd)/mass  (nb from bf16 A rows) ----
    {
        int p = tid >> 5, cg = lane;
        int c0 = cg * 4;
        float im = smf[F_INVM + p];
        float gr[9];
        #pragma unroll
        for (int n = 0; n < 9; ++n) gr[n] = smf[F_GATE + p*9 + n];
        float s0 = 0, s1 = 0, s2 = 0, s3 = 0;
        #pragma unroll
        for (int n = 0; n < 9; ++n) {
            const char* row = smem + A_OFFB + (p*9 + n)*ROWB;
            uint2 u = *(const uint2*)(row + c0*2);
            __nv_bfloat162 lo = *reinterpret_cast<__nv_bfloat162*>(&u.x);
            __nv_bfloat162 hi = *reinterpret_cast<__nv_bfloat162*>(&u.y);
            s0 += gr[n] * __bfloat162float(lo.x);
            s1 += gr[n] * __bfloat162float(lo.y);
            s2 += gr[n] * __bfloat162float(hi.x);
            s3 += gr[n] * __bfloat162float(hi.y);
        }
        wsS[p*CC + c0]     = s0 * im;
        wsS[p*CC + c0 + 1] = s1 * im;
        wsS[p*CC + c0 + 2] = s2 * im;
        wsS[p*CC + c0 + 3] = s3 * im;
    }
    __syncthreads();

    // ---- message = ws @ vW + vb*(sum_gate/mass) ----
    {
        int p = tid >> 5, dg = lane;
        int d0 = dg * 4;
        float coef = smf[F_SG + p] * smf[F_INVM + p];
        float a0 = 0, a1 = 0, a2 = 0, a3 = 0;
        const float* wsp = wsS + p*CC;
        #pragma unroll 4
        for (int c = 0; c < CC; ++c) {
            float w = wsp[c];
            float4 v = *reinterpret_cast<const float4*>(vW + c*CC + d0);
            a0 = fmaf(w, v.x, a0); a1 = fmaf(w, v.y, a1);
            a2 = fmaf(w, v.z, a2); a3 = fmaf(w, v.w, a3);
        }
        __syncthreads();   // all A-region reads (ws) done before msgS overwrite
        msgS[p*CC + d0]     = a0 + vb[d0]     * coef;
        msgS[p*CC + d0 + 1] = a1 + vb[d0 + 1] * coef;
        msgS[p*CC + d0 + 2] = a2 + vb[d0 + 2] * coef;
        msgS[p*CC + d0 + 3] = a3 + vb[d0 + 3] * coef;
    }
    __syncthreads();

    // ---- u = tokens + message @ oW + ob ----
    {
        int p = tid >> 5, dg = lane;
        int d0 = dg * 4;
        long grow = (long)(rowbase + p) * CC;
        float a0 = 0, a1 = 0, a2 = 0, a3 = 0;
        const float* mp = msgS + p*CC;
        #pragma unroll 4
        for (int c = 0; c < CC; ++c) {
            float w = mp[c];
            float4 v = *reinterpret_cast<const float4*>(oW + c*CC + d0);
            a0 = fmaf(w, v.x, a0); a1 = fmaf(w, v.y, a1);
            a2 = fmaf(w, v.z, a2); a3 = fmaf(w, v.w, a3);
        }
        uS[p*CC + d0]     = tokens[grow + d0]     + a0 + ob[d0];
        uS[p*CC + d0 + 1] = tokens[grow + d0 + 1] + a1 + ob[d0 + 1];
        uS[p*CC + d0 + 2] = tokens[grow + d0 + 2] + a2 + ob[d0 + 2];
        uS[p*CC + d0 + 3] = tokens[grow + d0 + 3] + a3 + ob[d0 + 3];
    }
    __syncthreads();

    // ---- LN2 + store (warp per position) ----
    {
        int p = warp;
        float4 x = reinterpret_cast<const float4*>(uS + p*CC)[lane];
        float s = x.x + x.y + x.z + x.w;
        #pragma unroll
        for (int o = 16; o; o >>= 1) s += __shfl_xor_sync(0xffffffffu, s, o);
        float m = s * (1.0f/128.0f);
        float dx = x.x - m, dy = x.y - m, dz = x.z - m, dw = x.w - m;
        float v = dx*dx + dy*dy + dz*dz + dw*dw;
        #pragma unroll
        for (int o = 16; o; o >>= 1) v += __shfl_xor_sync(0xffffffffu, v, o);
        float rs = rsqrtf(v * (1.0f/128.0f) + 1e-5f);
        int c = lane * 4;
        float4 o4;
        o4.x = dx*rs*ln2_g[c+0] + ln2_b[c+0];
        o4.y = dy*rs*ln2_g[c+1] + ln2_b[c+1];
        o4.z = dz*rs*ln2_g[c+2] + ln2_b[c+2];
        o4.w = dw*rs*ln2_g[c+3] + ln2_b[c+3];
        reinterpret_cast<float4*>(out + (long)(rowbase + p)*CC)[lane] = o4;
    }
}

// ---------------- launch ----------------
extern "C" void kernel_launch(void* const* d_in, const int* in_sizes, int n_in,
                              void* d_out, int out_size) {
    const float* tokens = (const float*)d_in[0];
    const float* ln1_g  = (const float*)d_in[1];
    const float* ln1_b  = (const float*)d_in[2];
    const float* ln2_g  = (const float*)d_in[3];
    const float* ln2_b  = (const float*)d_in[4];
    const float* rel_pos= (const float*)d_in[5];
    const float* dW1    = (const float*)d_in[6];
    const float* db1    = (const float*)d_in[7];
    const float* dW2    = (const float*)d_in[8];
    const float* db2    = (const float*)d_in[9];
    const float* rW1    = (const float*)d_in[10];
    const float* rb1    = (const float*)d_in[11];
    const float* rW2    = (const float*)d_in[12];
    const float* rb2    = (const float*)d_in[13];
    const float* vW     = (const float*)d_in[14];
    const float* vb     = (const float*)d_in[15];
    const float* oW     = (const float*)d_in[16];
    const float* ob     = (const float*)d_in[17];
    const float* gamma  = (const float*)d_in[18];
    const float* lam    = (const float*)d_in[19];
    const float* ebias  = (const float*)d_in[20];
    float* out = (float*)d_out;

    setup_kernel<<<4328, 256>>>(tokens, ln1_g, ln1_b, dW1, db1, rW1, rb1, rel_pos);
    cudaFuncSetAttribute(eml_main_kernel, cudaFuncAttributeMaxDynamicSharedMemorySize, SMEM_TOTAL);
    eml_main_kernel<<<(BB*HH*WW)/TILE_P, NT, SMEM_TOTAL>>>(tokens, ln2_g, ln2_b, dW2, db2,
                                                           rW2, rb2, vW, vb, oW, ob,
                                                           gamma, lam, ebias, out);
}

// round 11
// speedup vs baseline: 1.9422x; 1.1672x over previous
#include <cuda_runtime.h>
#include <cuda_bf16.h>
#include <cstdint>

#define BB 2
#define HH 128
#define WW 128
#define CC 128
#define NBR 9
#define TILE_P 16
#define NEDGE 144
#define NT 512

#define KP 152                 /* padded A cols */
#define ROWB (KP*2)            /* 304 B rows: 304 mod 128 = 48 -> conflict-free ldmatrix */

// smem byte layout (total 72448)
#define CU_OFFB   4096                        // [16][256] f32 cu table
#define CEN_OFFB  (CU_OFFB + 16384)           // [16][128] f32 centers (reused as wsS)
#define A_OFFB    (CEN_OFFB + 8192)           // A: 144 x 152 bf16 = 43776
#define SMEM_TOTAL (A_OFFB + 43776)
// misc float indices in smf[0..1023]
#define F_PART  0       /* [144][4] */
#define F_GATE  576
#define F_SG    720
#define F_INVM  736
#define F_W2    768     /* [256]: dW2 | rW2 */

// ---- device scratch ----
__device__ float g_norm[BB*HH*WW*CC];
__device__ float g_Ud[CC*CC], g_Ur[CC*CC];
__device__ uint4 g_Bfrag[16*9*32];           // [nq*4+nb][k][lane] B fragments

// ---- helpers ----
__device__ __forceinline__ float gelu_exact(float x) {
    return 0.5f * x * (1.0f + erff(x * 0.70710678118654752f));
}
__device__ __forceinline__ uint32_t smem_u32(const void* p) {
    uint32_t a;
    asm("{ .reg .u64 t; cvta.to.shared.u64 t, %1; cvt.u32.u64 %0, t; }" : "=r"(a) : "l"(p));
    return a;
}
__device__ __forceinline__ void ldm_x4(uint32_t* r, uint32_t addr) {
    asm volatile("ldmatrix.sync.aligned.m8n8.x4.shared.b16 {%0,%1,%2,%3}, [%4];"
        : "=r"(r[0]), "=r"(r[1]), "=r"(r[2]), "=r"(r[3]) : "r"(addr));
}
__device__ __forceinline__ void mma16816(float* c, const uint32_t* a, uint32_t b0, uint32_t b1) {
    asm volatile("mma.sync.aligned.m16n8k16.row.col.f32.bf16.bf16.f32 "
        "{%0,%1,%2,%3}, {%4,%5,%6,%7}, {%8,%9}, {%0,%1,%2,%3};"
        : "+f"(c[0]), "+f"(c[1]), "+f"(c[2]), "+f"(c[3])
        : "r"(a[0]), "r"(a[1]), "r"(a[2]), "r"(a[3]), "r"(b0), "r"(b1));
}

__device__ __forceinline__ float b_val(int j, int c,
        const float* dW1, const float* db1, const float* rW1, const float* rb1,
        const float* rel_pos) {
    float val = 0.0f;
    if (c < 128) {
        val = (j < 128) ? dW1[(128 + c)*CC + j]       - dW1[(256 + c)*CC + j]
                        : rW1[(128 + c)*CC + (j-128)] - rW1[(256 + c)*CC + (j-128)];
    } else if (c < 137) {
        int n = c - 128;
        if (j < 128) {
            float bd = db1[j];
            #pragma unroll
            for (int r = 0; r < 8; ++r) bd += rel_pos[n*8 + r] * dW1[(384 + r)*CC + j];
            val = bd;
        } else {
            float br = rb1[j - 128];
            #pragma unroll
            for (int r = 0; r < 8; ++r) br += rel_pos[n*8 + r] * rW1[(384 + r)*CC + (j-128)];
            val = br;
        }
    }
    return val;
}

// ================= setup 1: LN1 + U fold =================
__global__ void setup_kernel(const float* __restrict__ tokens,
                             const float* __restrict__ g, const float* __restrict__ b,
                             const float* __restrict__ dW1, const float* __restrict__ rW1) {
    if (blockIdx.x < 4096) {
        int warp = threadIdx.x >> 5, lane = threadIdx.x & 31;
        int row  = blockIdx.x * 8 + warp;
        float4 x = reinterpret_cast<const float4*>(tokens + (long)row*CC)[lane];
        float s = x.x + x.y + x.z + x.w;
        #pragma unroll
        for (int o = 16; o; o >>= 1) s += __shfl_xor_sync(0xffffffffu, s, o);
        float m = s * (1.0f/128.0f);
        float dx = x.x - m, dy = x.y - m, dz = x.z - m, dw = x.w - m;
        float v = dx*dx + dy*dy + dz*dz + dw*dw;
        #pragma unroll
        for (int o = 16; o; o >>= 1) v += __shfl_xor_sync(0xffffffffu, v, o);
        float rs = rsqrtf(v * (1.0f/128.0f) + 1e-5f);
        int c = lane * 4;
        float4 o4;
        o4.x = dx*rs*g[c+0] + b[c+0];
        o4.y = dy*rs*g[c+1] + b[c+1];
        o4.z = dz*rs*g[c+2] + b[c+2];
        o4.w = dw*rs*g[c+3] + b[c+3];
        reinterpret_cast<float4*>(g_norm + (long)row*CC)[lane] = o4;
    } else {
        int idx = (blockIdx.x - 4096) * 256 + threadIdx.x;   // < 16384
        int c = idx >> 7, j = idx & 127;
        g_Ud[idx] = dW1[c*CC + j] + dW1[(256 + c)*CC + j];
        g_Ur[idx] = rW1[c*CC + j] + rW1[(256 + c)*CC + j];
    }
}

// ================= setup 2: build B fragments (1 block) =================
__global__ void bfrag_kernel(const float* __restrict__ dW1, const float* __restrict__ db1,
                             const float* __restrict__ rW1, const float* __restrict__ rb1,
                             const float* __restrict__ rel_pos) {
    extern __shared__ char s[];
    const int tid = threadIdx.x;
    // stage B[256][152] bf16, stride 304B (cols >=137 zero)
    for (int idx = tid; idx < 256*KP; idx += NT) {
        int j = idx / KP, c = idx - (idx / KP)*KP;
        *(__nv_bfloat16*)(s + j*ROWB + c*2) =
            __float2bfloat16(b_val(j, c, dW1, db1, rW1, rb1, rel_pos));
    }
    __syncthreads();
    const int warp = tid >> 5, lane = tid & 31;   // warp = nq*4+nb
    int nq = warp >> 2, nb = warp & 3;
    int n0 = nq*64 + nb*16;
    uint32_t baddr = smem_u32(s) + (uint32_t)((n0 + (lane & 7) + ((lane >> 4) << 3))*ROWB
                   + (((lane >> 3) & 1) << 4));
    #pragma unroll
    for (int k = 0; k < 9; ++k) {
        uint32_t bf[4];
        ldm_x4(bf, baddr + k*32);
        g_Bfrag[(warp*9 + k)*32 + lane] = make_uint4(bf[0], bf[1], bf[2], bf[3]);
    }
}

// ================= main fused kernel: CTA = 16 positions =================
__global__ __launch_bounds__(NT, 2)
void eml_main_kernel(const float* __restrict__ tokens,
                     const float* __restrict__ ln2_g, const float* __restrict__ ln2_b,
                     const float* __restrict__ dW2, const float* __restrict__ db2,
                     const float* __restrict__ rW2, const float* __restrict__ rb2,
                     const float* __restrict__ vW,  const float* __restrict__ vb,
                     const float* __restrict__ oW,  const float* __restrict__ ob,
                     const float* __restrict__ p_gamma, const float* __restrict__ p_lam,
                     const float* __restrict__ p_bias,
                     float* __restrict__ out) {
    extern __shared__ char smem[];
    float* smf  = (float*)smem;
    float* cuS  = (float*)(smem + CU_OFFB);       // [16][256]
    float* cenS = (float*)(smem + CEN_OFFB);      // [16][128], reused as wsS
    float* wsS  = cenS;
    float* msgS = (float*)(smem + A_OFFB);        // reuse A region
    float* uS   = msgS + 2048;
    const uint32_t smb = smem_u32(smem);

    const int tid  = threadIdx.x;
    const int warp = tid >> 5, lane = tid & 31;
    const int blk = blockIdx.x;
    const int b   = blk >> 10;
    const int t   = blk & 1023;
    const int h   = t >> 3;
    const int w0  = (t & 7) << 4;
    const int rowbase = (b*HH + h)*WW + w0;

    // ---- phase 0: zero A, stage cen + w2 ----
    {
        uint4 z = make_uint4(0, 0, 0, 0);
        uint4* adst = (uint4*)(smem + A_OFFB);
        #pragma unroll 2
        for (int i = tid; i < 43776/16; i += NT) adst[i] = z;
        for (int i = tid; i < TILE_P*CC; i += NT) cenS[i] = g_norm[(long)rowbase*CC + i];
        if (tid < 256) smf[F_W2 + tid] = (tid < 128) ? dW2[tid] : rW2[tid - 128];
    }
    __syncthreads();

    // ---- phase 1: gather scrambled nbhd -> A (bf16); one-hot(n); cu -> cuS f32 ----
    for (int idx = tid; idx < TILE_P*NBR*CC; idx += NT) {
        int p  = idx / 1152;
        int r0 = idx - p*1152;
        int s  = r0 >> 7;
        int c2 = r0 & 127;
        int f  = c2*9 + s;
        int n  = f >> 7;
        int c  = f & 127;
        int di = s / 3;
        int dj = s - di*3;
        int hh = h + di - 1;
        int ww = w0 + p + dj - 1;
        float val = 0.0f;
        if ((unsigned)hh < HH && (unsigned)ww < WW)
            val = g_norm[(((long)(b*HH + hh)*WW + ww))*CC + c2];
        int e = p*9 + n;
        *(__nv_bfloat16*)(smem + A_OFFB + e*ROWB + c*2) = __float2bfloat16(val);
    }
    if (tid < NEDGE) {
        int n = tid - (tid / 9)*9;
        *(__nv_bfloat16*)(smem + A_OFFB + tid*ROWB + (128 + n)*2) = __float2bfloat16(1.0f);
    }
    // cu[p][j] = center @ [Ud|Ur], f32
    {
        const int jj = tid & 255;
        const int ph = tid >> 8;              // 0..1 -> 8 positions each
        const float* Up = (jj < 128) ? (g_Ud + jj) : (g_Ur + jj - 128);
        float acc[8];
        #pragma unroll
        for (int i = 0; i < 8; ++i) acc[i] = 0.0f;
        for (int c0 = 0; c0 < CC; c0 += 4) {
            float4 cq[8];
            #pragma unroll
            for (int i = 0; i < 8; ++i)
                cq[i] = *reinterpret_cast<const float4*>(cenS + (ph*8 + i)*CC + c0);
            #pragma unroll
            for (int cc = 0; cc < 4; ++cc) {
                float u = Up[(c0 + cc)*CC];
                #pragma unroll
                for (int i = 0; i < 8; ++i) {
                    float cv = (cc == 0) ? cq[i].x : (cc == 1) ? cq[i].y
                             : (cc == 2) ? cq[i].z : cq[i].w;
                    acc[i] = fmaf(cv, u, acc[i]);
                }
            }
        }
        #pragma unroll
        for (int i = 0; i < 8; ++i)
            cuS[(ph*8 + i)*256 + jj] = acc[i];
    }
    __syncthreads();

    // ---- phase 2: edge GEMM (A smem x B gmem-fragments); 36 tasks over 16 warps ----
    {
        const uint32_t Abase = smb + A_OFFB;
        for (int task = warp; task < 36; task += 16) {
            int mt = task % 9, nq = task / 9;
            int m0 = mt * 16;
            int r0 = m0 + (lane >> 2);
            int p0 = r0 / 9, p1 = (r0 + 8) / 9;
            uint32_t aaddr = Abase + (m0 + (lane & 15))*ROWB + ((lane >> 4) << 4);
            float acc[4][8];
            #pragma unroll
            for (int nb = 0; nb < 4; ++nb)
                #pragma unroll
                for (int q = 0; q < 8; ++q) acc[nb][q] = 0.0f;
            const uint4* bp = g_Bfrag + (nq*4)*9*32 + lane;
            #pragma unroll
            for (int k = 0; k < 9; ++k) {
                uint32_t af[4];
                ldm_x4(af, aaddr + k*32);
                #pragma unroll
                for (int nb = 0; nb < 4; ++nb) {
                    uint4 bf = bp[(nb*9 + k)*32];
                    mma16816(acc[nb],     af, bf.x, bf.y);
                    mma16816(acc[nb] + 4, af, bf.z, bf.w);
                }
            }
            float part0 = 0.0f, part1 = 0.0f;
            const float* w2q = smf + F_W2 + nq*64;
            #pragma unroll
            for (int nb = 0; nb < 4; ++nb) {
                int jl = nb*16 + (lane & 3)*2;
                int jg = nq*64 + jl;
                const float* cu0 = cuS + p0*256 + jg;
                const float* cu1 = cuS + p1*256 + jg;
                part0 += gelu_exact(acc[nb][0] + cu0[0])*w2q[jl]
                       + gelu_exact(acc[nb][1] + cu0[1])*w2q[jl+1]
                       + gelu_exact(acc[nb][4] + cu0[8])*w2q[jl+8]
                       + gelu_exact(acc[nb][5] + cu0[9])*w2q[jl+9];
                part1 += gelu_exact(acc[nb][2] + cu1[0])*w2q[jl]
                       + gelu_exact(acc[nb][3] + cu1[1])*w2q[jl+1]
                       + gelu_exact(acc[nb][6] + cu1[8])*w2q[jl+8]
                       + gelu_exact(acc[nb][7] + cu1[9])*w2q[jl+9];
            }
            part0 += __shfl_xor_sync(0xffffffffu, part0, 1);
            part0 += __shfl_xor_sync(0xffffffffu, part0, 2);
            part1 += __shfl_xor_sync(0xffffffffu, part1, 1);
            part1 += __shfl_xor_sync(0xffffffffu, part1, 2);
            if ((lane & 3) == 0) {
                smf[F_PART + r0*4 + nq]       = part0;
                smf[F_PART + (r0 + 8)*4 + nq] = part1;
            }
        }
    }
    __syncthreads();

    // ---- EML gate ----
    const float gamma = *p_gamma, lam = *p_lam, ebias = *p_bias;
    if (tid < NEDGE) {
        float d = smf[F_PART + tid*4 + 0] + smf[F_PART + tid*4 + 1] + db2[0];
        float r = smf[F_PART + tid*4 + 2] + smf[F_PART + tid*4 + 3] + rb2[0];
        float sp = fmaxf(r, 0.0f) + log1pf(expf(-fabsf(r)));
        float en = gamma * d / (lam * sp + 1e-6f) + ebias;
        en = fminf(fmaxf(en, -3.0f), 3.0f);
        smf[F_GATE + tid] = 1.0f / (1.0f + expf(-en));
    }
    __syncthreads();
    if (tid < TILE_P) {
        float s = 0.0f;
        #pragma unroll
        for (int n = 0; n < 9; ++n) s += smf[F_GATE + tid*9 + n];
        smf[F_SG + tid]   = s;
        smf[F_INVM + tid] = 1.0f / fmaxf(s, 1e-6f);
    }
    __syncthreads();

    // ---- ws[p][c] = (sum_n gate*nbhd)/mass ----
    {
        int p = tid >> 5;
        int c0 = lane * 4;
        float im = smf[F_INVM + p];
        float gr[9];
        #pragma unroll
        for (int n = 0; n < 9; ++n) gr[n] = smf[F_GATE + p*9 + n];
        float s0 = 0, s1 = 0, s2 = 0, s3 = 0;
        #pragma unroll
        for (int n = 0; n < 9; ++n) {
            const char* row = smem + A_OFFB + (p*9 + n)*ROWB;
            uint2 u = *(const uint2*)(row + c0*2);
            __nv_bfloat162 lo = *reinterpret_cast<__nv_bfloat162*>(&u.x);
            __nv_bfloat162 hi = *reinterpret_cast<__nv_bfloat162*>(&u.y);
            s0 += gr[n] * __bfloat162float(lo.x);
            s1 += gr[n] * __bfloat162float(lo.y);
            s2 += gr[n] * __bfloat162float(hi.x);
            s3 += gr[n] * __bfloat162float(hi.y);
        }
        __syncthreads();   // A reads done before wsS... (wsS=cenS distinct; sync guards msg overwrite of A)
        wsS[p*CC + c0]     = s0 * im;
        wsS[p*CC + c0 + 1] = s1 * im;
        wsS[p*CC + c0 + 2] = s2 * im;
        wsS[p*CC + c0 + 3] = s3 * im;
    }
    __syncthreads();

    // ---- message = ws @ vW + vb*(sum_gate/mass) ----
    {
        int p = tid >> 5;
        int d0 = lane * 4;
        float coef = smf[F_SG + p] * smf[F_INVM + p];
        float a0 = 0, a1 = 0, a2 = 0, a3 = 0;
        const float* wsp = wsS + p*CC;
        #pragma unroll 4
        for (int c = 0; c < CC; ++c) {
            float w = wsp[c];
            float4 v = *reinterpret_cast<const float4*>(vW + c*CC + d0);
            a0 = fmaf(w, v.x, a0); a1 = fmaf(w, v.y, a1);
            a2 = fmaf(w, v.z, a2); a3 = fmaf(w, v.w, a3);
        }
        msgS[p*CC + d0]     = a0 + vb[d0]     * coef;
        msgS[p*CC + d0 + 1] = a1 + vb[d0 + 1] * coef;
        msgS[p*CC + d0 + 2] = a2 + vb[d0 + 2] * coef;
        msgS[p*CC + d0 + 3] = a3 + vb[d0 + 3] * coef;
    }
    __syncthreads();

    // ---- u = tokens + message @ oW + ob ----
    {
        int p = tid >> 5;
        int d0 = lane * 4;
        long grow = (long)(rowbase + p) * CC;
        float a0 = 0, a1 = 0, a2 = 0, a3 = 0;
        const float* mp = msgS + p*CC;
        #pragma unroll 4
        for (int c = 0; c < CC; ++c) {
            float w = mp[c];
            float4 v = *reinterpret_cast<const float4*>(oW + c*CC + d0);
            a0 = fmaf(w, v.x, a0); a1 = fmaf(w, v.y, a1);
            a2 = fmaf(w, v.z, a2); a3 = fmaf(w, v.w, a3);
        }
        __syncthreads();   // msgS reads done before uS writes (uS overlaps region above msgS)
        uS[p*CC + d0]     = tokens[grow + d0]     + a0 + ob[d0];
        uS[p*CC + d0 + 1] = tokens[grow + d0 + 1] + a1 + ob[d0 + 1];
        uS[p*CC + d0 + 2] = tokens[grow + d0 + 2] + a2 + ob[d0 + 2];
        uS[p*CC + d0 + 3] = tokens[grow + d0 + 3] + a3 + ob[d0 + 3];
    }
    __syncthreads();

    // ---- LN2 + store (warp per position) ----
    {
        int p = warp;
        float4 x = reinterpret_cast<const float4*>(uS + p*CC)[lane];
        float s = x.x + x.y + x.z + x.w;
        #pragma unroll
        for (int o = 16; o; o >>= 1) s += __shfl_xor_sync(0xffffffffu, s, o);
        float m = s * (1.0f/128.0f);
        float dx = x.x - m, dy = x.y - m, dz = x.z - m, dw = x.w - m;
        float v = dx*dx + dy*dy + dz*dz + dw*dw;
        #pragma unroll
        for (int o = 16; o; o >>= 1) v += __shfl_xor_sync(0xffffffffu, v, o);
        float rs = rsqrtf(v * (1.0f/128.0f) + 1e-5f);
        int c = lane * 4;
        float4 o4;
        o4.x = dx*rs*ln2_g[c+0] + ln2_b[c+0];
        o4.y = dy*rs*ln2_g[c+1] + ln2_b[c+1];
        o4.z = dz*rs*ln2_g[c+2] + ln2_b[c+2];
        o4.w = dw*rs*ln2_g[c+3] + ln2_b[c+3];
        reinterpret_cast<float4*>(out + (long)(rowbase + p)*CC)[lane] = o4;
    }
}

// ---------------- launch ----------------
extern "C" void kernel_launch(void* const* d_in, const int* in_sizes, int n_in,
                              void* d_out, int out_size) {
    const float* tokens = (const float*)d_in[0];
    const float* ln1_g  = (const float*)d_in[1];
    const float* ln1_b  = (const float*)d_in[2];
    const float* ln2_g  = (const float*)d_in[3];
    const float* ln2_b  = (const float*)d_in[4];
    const float* rel_pos= (const float*)d_in[5];
    const float* dW1    = (const float*)d_in[6];
    const float* db1    = (const float*)d_in[7];
    const float* dW2    = (const float*)d_in[8];
    const float* db2    = (const float*)d_in[9];
    const float* rW1    = (const float*)d_in[10];
    const float* rb1    = (const float*)d_in[11];
    const float* rW2    = (const float*)d_in[12];
    const float* rb2    = (const float*)d_in[13];
    const float* vW     = (const float*)d_in[14];
    const float* vb     = (const float*)d_in[15];
    const float* oW     = (const float*)d_in[16];
    const float* ob     = (const float*)d_in[17];
    const float* gamma  = (const float*)d_in[18];
    const float* lam    = (const float*)d_in[19];
    const float* ebias  = (const float*)d_in[20];
    float* out = (float*)d_out;

    setup_kernel<<<4160, 256>>>(tokens, ln1_g, ln1_b, dW1, rW1);
    cudaFuncSetAttribute(bfrag_kernel, cudaFuncAttributeMaxDynamicSharedMemorySize, 256*ROWB);
    bfrag_kernel<<<1, NT, 256*ROWB>>>(dW1, db1, rW1, rb1, rel_pos);
    cudaFuncSetAttribute(eml_main_kernel, cudaFuncAttributeMaxDynamicSharedMemorySize, SMEM_TOTAL);
    eml_main_kernel<<<(BB*HH*WW)/TILE_P, NT, SMEM_TOTAL>>>(tokens, ln2_g, ln2_b, dW2, db2,
                                                           rW2, rb2, vW, vb, oW, ob,
                                                           gamma, lam, ebias, out);
}

// round 12
// speedup vs baseline: 1.9937x; 1.0265x over previous
#include <cuda_runtime.h>
#include <cuda_bf16.h>
#include <cstdint>

#define BB 2
#define HH 128
#define WW 128
#define CC 128
#define NBR 9
#define TILE_P 16
#define NEDGE 144
#define NT 512

#define KP 152                 /* padded edge-A cols */
#define ROWB (KP*2)            /* 304 B rows (conflict-free ldmatrix) */
#define CROWB 272              /* cen/ws tile row stride bytes (136 bf16 cols) */

// ---- smem float indices (misc block, 1280 floats = 5120 B) ----
#define F_PART  0       /* [144][4] */
#define F_GATE  576
#define F_SG    720
#define F_INVM  736
#define F_W2    768     /* [256]: dW2 | rW2 */
#define F_VBO   1024    /* [128] vb@oW */
#define F_OB    1152    /* [128] ob */
// ---- smem byte offsets ----
#define CU_OFFB   5120                        // [16][256] f32 cu table (16384)
#define CW_OFFB   (CU_OFFB + 16384)           // cen/ws bf16 tile 16 x CROWB (4352)
#define A_OFFB    (CW_OFFB + 4352)            // edge A: 144 x 304 = 43776
#define SMEM_TOTAL (A_OFFB + 43776)           // 69632

// ---- device scratch ----
__device__ float g_norm[BB*HH*WW*CC];
__device__ float g_Wcomb[CC*CC];             // vW@oW f32
__device__ float g_vbo[CC];                  // vb@oW
__device__ uint32_t g_map[1152];             // gather map
__device__ uint4 g_Bfrag[16*9*32];           // edge B fragments
__device__ uint4 g_Ufrag[16*8*32];           // U (cu) B fragments
__device__ uint4 g_Wfrag[8*8*32];            // Wcomb B fragments

// ---- helpers ----
__device__ __forceinline__ float gelu_exact(float x) {
    return 0.5f * x * (1.0f + erff(x * 0.70710678118654752f));
}
__device__ __forceinline__ uint32_t smem_u32(const void* p) {
    uint32_t a;
    asm("{ .reg .u64 t; cvta.to.shared.u64 t, %1; cvt.u32.u64 %0, t; }" : "=r"(a) : "l"(p));
    return a;
}
__device__ __forceinline__ void ldm_x4(uint32_t* r, uint32_t addr) {
    asm volatile("ldmatrix.sync.aligned.m8n8.x4.shared.b16 {%0,%1,%2,%3}, [%4];"
        : "=r"(r[0]), "=r"(r[1]), "=r"(r[2]), "=r"(r[3]) : "r"(addr));
}
__device__ __forceinline__ void mma16816(float* c, const uint32_t* a, uint32_t b0, uint32_t b1) {
    asm volatile("mma.sync.aligned.m16n8k16.row.col.f32.bf16.bf16.f32 "
        "{%0,%1,%2,%3}, {%4,%5,%6,%7}, {%8,%9}, {%0,%1,%2,%3};"
        : "+f"(c[0]), "+f"(c[1]), "+f"(c[2]), "+f"(c[3])
        : "r"(a[0]), "r"(a[1]), "r"(a[2]), "r"(a[3]), "r"(b0), "r"(b1));
}

__device__ __forceinline__ float b_val(int j, int c,
        const float* dW1, const float* db1, const float* rW1, const float* rb1,
        const float* rel_pos) {
    float val = 0.0f;
    if (c < 128) {
        val = (j < 128) ? dW1[(128 + c)*CC + j]       - dW1[(256 + c)*CC + j]
                        : rW1[(128 + c)*CC + (j-128)] - rW1[(256 + c)*CC + (j-128)];
    } else if (c < 137) {
        int n = c - 128;
        if (j < 128) {
            float bd = db1[j];
            #pragma unroll
            for (int r = 0; r < 8; ++r) bd += rel_pos[n*8 + r] * dW1[(384 + r)*CC + j];
            val = bd;
        } else {
            float br = rb1[j - 128];
            #pragma unroll
            for (int r = 0; r < 8; ++r) br += rel_pos[n*8 + r] * rW1[(384 + r)*CC + (j-128)];
            val = br;
        }
    }
    return val;
}

// ================= setup 1: LN1 + Wcomb + vbo + map =================
__global__ void setup_kernel(const float* __restrict__ tokens,
                             const float* __restrict__ g, const float* __restrict__ b,
                             const float* __restrict__ vW, const float* __restrict__ oW,
                             const float* __restrict__ vb) {
    if (blockIdx.x < 4096) {
        int warp = threadIdx.x >> 5, lane = threadIdx.x & 31;
        int row  = blockIdx.x * 8 + warp;
        float4 x = reinterpret_cast<const float4*>(tokens + (long)row*CC)[lane];
        float s = x.x + x.y + x.z + x.w;
        #pragma unroll
        for (int o = 16; o; o >>= 1) s += __shfl_xor_sync(0xffffffffu, s, o);
        float m = s * (1.0f/128.0f);
        float dx = x.x - m, dy = x.y - m, dz = x.z - m, dw = x.w - m;
        float v = dx*dx + dy*dy + dz*dz + dw*dw;
        #pragma unroll
        for (int o = 16; o; o >>= 1) v += __shfl_xor_sync(0xffffffffu, v, o);
        float rs = rsqrtf(v * (1.0f/128.0f) + 1e-5f);
        int c = lane * 4;
        float4 o4;
        o4.x = dx*rs*g[c+0] + b[c+0];
        o4.y = dy*rs*g[c+1] + b[c+1];
        o4.z = dz*rs*g[c+2] + b[c+2];
        o4.w = dw*rs*g[c+3] + b[c+3];
        reinterpret_cast<float4*>(g_norm + (long)row*CC)[lane] = o4;
    } else if (blockIdx.x < 4160) {
        // Wcomb = vW @ oW (f32)
        int o = (blockIdx.x - 4096) * 256 + threadIdx.x;     // < 16384
        int c = o >> 7, d = o & 127;
        float s = 0.0f;
        #pragma unroll 4
        for (int e = 0; e < 128; ++e) s = fmaf(vW[c*CC + e], oW[e*CC + d], s);
        g_Wcomb[o] = s;
    } else if (blockIdx.x == 4160) {
        int d = threadIdx.x;
        if (d < 128) {
            float s = 0.0f;
            #pragma unroll 4
            for (int e = 0; e < 128; ++e) s = fmaf(vb[e], oW[e*CC + d], s);
            g_vbo[d] = s;
        }
    } else {
        // gather map: r0 -> (dst byte off, di, dj, c2)
        for (int r0 = threadIdx.x; r0 < 1152; r0 += 256) {
            int s  = r0 >> 7;
            int c2 = r0 & 127;
            int f  = c2*9 + s;
            int n  = f >> 7;
            int c  = f & 127;
            int di = s / 3;
            int dj = s - di*3;
            uint32_t dst = (uint32_t)(n*ROWB + c*2);
            g_map[r0] = (dst << 11) | ((uint32_t)di << 9) | ((uint32_t)dj << 7) | (uint32_t)c2;
        }
    }
}

// ================= setup 2: build all static B fragments (1 block) =================
__global__ void bfrag_kernel(const float* __restrict__ dW1, const float* __restrict__ db1,
                             const float* __restrict__ rW1, const float* __restrict__ rb1,
                             const float* __restrict__ rel_pos) {
    extern __shared__ char s[];
    const int tid = threadIdx.x;
    const int warp = tid >> 5, lane = tid & 31;
    const uint32_t sb = smem_u32(s);

    // --- stage edge B [256][KP] stride ROWB, frag -> g_Bfrag ---
    for (int idx = tid; idx < 256*KP; idx += NT) {
        int j = idx / KP, c = idx - (idx / KP)*KP;
        *(__nv_bfloat16*)(s + j*ROWB + c*2) =
            __float2bfloat16(b_val(j, c, dW1, db1, rW1, rb1, rel_pos));
    }
    __syncthreads();
    {
        int nq = warp >> 2, nb = warp & 3;
        int n0 = nq*64 + nb*16;
        uint32_t baddr = sb + (uint32_t)((n0 + (lane & 7) + ((lane >> 4) << 3))*ROWB
                       + (((lane >> 3) & 1) << 4));
        #pragma unroll
        for (int k = 0; k < 9; ++k) {
            uint32_t bf[4];
            ldm_x4(bf, baddr + k*32);
            g_Bfrag[(warp*9 + k)*32 + lane] = make_uint4(bf[0], bf[1], bf[2], bf[3]);
        }
    }
    __syncthreads();

    // --- stage U [256 j][128 c] stride CROWB, frag -> g_Ufrag ---
    for (int idx = tid; idx < 256*128; idx += NT) {
        int j = idx >> 7, c = idx & 127;
        float val = (j < 128) ? dW1[c*CC + j]       + dW1[(256 + c)*CC + j]
                              : rW1[c*CC + (j-128)] + rW1[(256 + c)*CC + (j-128)];
        *(__nv_bfloat16*)(s + j*CROWB + c*2) = __float2bfloat16(val);
    }
    __syncthreads();
    {
        int n0 = warp * 16;
        uint32_t baddr = sb + (uint32_t)((n0 + (lane & 7) + ((lane >> 4) << 3))*CROWB
                       + (((lane >> 3) & 1) << 4));
        #pragma unroll
        for (int k = 0; k < 8; ++k) {
            uint32_t bf[4];
            ldm_x4(bf, baddr + k*32);
            g_Ufrag[(warp*8 + k)*32 + lane] = make_uint4(bf[0], bf[1], bf[2], bf[3]);
        }
    }
    __syncthreads();

    // --- stage Wcomb as B [128 d][128 c], frag -> g_Wfrag ---
    for (int idx = tid; idx < 128*128; idx += NT) {
        int j = idx >> 7, c = idx & 127;                 // j = output d, c = k
        *(__nv_bfloat16*)(s + j*CROWB + c*2) = __float2bfloat16(g_Wcomb[c*CC + j]);
    }
    __syncthreads();
    if (warp < 8) {
        int n0 = warp * 16;
        uint32_t baddr = sb + (uint32_t)((n0 + (lane & 7) + ((lane >> 4) << 3))*CROWB
                       + (((lane >> 3) & 1) << 4));
        #pragma unroll
        for (int k = 0; k < 8; ++k) {
            uint32_t bf[4];
            ldm_x4(bf, baddr + k*32);
            g_Wfrag[(warp*8 + k)*32 + lane] = make_uint4(bf[0], bf[1], bf[2], bf[3]);
        }
    }
}

// ================= main fused kernel: CTA = 16 positions =================
__global__ __launch_bounds__(NT, 2)
void eml_main_kernel(const float* __restrict__ tokens,
                     const float* __restrict__ ln2_g, const float* __restrict__ ln2_b,
                     const float* __restrict__ dW2, const float* __restrict__ db2,
                     const float* __restrict__ rW2, const float* __restrict__ rb2,
                     const float* __restrict__ ob,
                     const float* __restrict__ p_gamma, const float* __restrict__ p_lam,
                     const float* __restrict__ p_bias,
                     float* __restrict__ out) {
    extern __shared__ char smem[];
    float* smf = (float*)smem;
    float* cuS = (float*)(smem + CU_OFFB);        // [16][256]
    float* uS  = (float*)(smem + A_OFFB);         // aliases edge A (dead by then)
    const uint32_t smb = smem_u32(smem);

    const int tid  = threadIdx.x;
    const int warp = tid >> 5, lane = tid & 31;
    const int blk = blockIdx.x;
    const int b   = blk >> 10;
    const int t   = blk & 1023;
    const int h   = t >> 3;
    const int w0  = (t & 7) << 4;
    const int rowbase = (b*HH + h)*WW + w0;

    // ---- phase 0: ext-col zero + one-hot; cen bf16 stage; w2/vbo/ob stage ----
    if (tid < NEDGE) {
        char* row = smem + A_OFFB + tid*ROWB;
        uint4 z = make_uint4(0, 0, 0, 0);
        *(uint4*)(row + 256) = z;
        *(uint4*)(row + 272) = z;
        *(uint4*)(row + 288) = z;
        int n = tid - (tid / 9)*9;
        *(__nv_bfloat16*)(row + (128 + n)*2) = __float2bfloat16(1.0f);
    }
    for (int i = tid; i < 1024; i += NT) {
        int p = i >> 6, cp = i & 63;
        float2 v = *(const float2*)(g_norm + (long)(rowbase + p)*CC + cp*2);
        *(__nv_bfloat162*)(smem + CW_OFFB + p*CROWB + cp*4) = __floats2bfloat162_rn(v.x, v.y);
    }
    if (tid < 256)      smf[F_W2 + tid] = (tid < 128) ? dW2[tid] : rW2[tid - 128];
    else if (tid < 384) smf[F_VBO + tid - 256] = g_vbo[tid - 256];
    else                smf[F_OB + tid - 384]  = ob[tid - 384];

    // ---- phase 1: map-based gather -> edge A bf16 ----
    for (int r0 = tid; r0 < 1152; r0 += NT) {
        uint32_t pk = g_map[r0];
        int c2 = pk & 127;
        int dj = (pk >> 7) & 3;
        int di = (pk >> 9) & 3;
        uint32_t dst = pk >> 11;
        int hh = h + di - 1;
        bool hok = (unsigned)hh < HH;
        long srow = (long)(b*HH + hh)*WW;
        char* dbase = smem + A_OFFB + dst;
        #pragma unroll
        for (int p = 0; p < 16; ++p) {
            int ww = w0 + p + dj - 1;
            float val = 0.0f;
            if (hok && (unsigned)ww < WW) val = g_norm[(srow + ww)*CC + c2];
            *(__nv_bfloat16*)(dbase + p*(9*ROWB)) = __float2bfloat16(val);
        }
    }
    __syncthreads();

    // ---- phase 2: cu GEMM (cen @ U), 16 warps x one n16-block ----
    {
        uint32_t aaddr = smb + CW_OFFB + (lane & 15)*CROWB + ((lane >> 4) << 4);
        uint32_t af[8][4];
        #pragma unroll
        for (int k = 0; k < 8; ++k) ldm_x4(af[k], aaddr + k*32);
        float cA[4] = {0,0,0,0}, cB[4] = {0,0,0,0};
        const uint4* up = g_Ufrag + (warp*8)*32 + lane;
        #pragma unroll
        for (int k = 0; k < 8; ++k) {
            uint4 bf = up[k*32];
            mma16816(cA, af[k], bf.x, bf.y);
            mma16816(cB, af[k], bf.z, bf.w);
        }
        int r = lane >> 2, jc = warp*16 + (lane & 3)*2;
        cuS[r*256 + jc]           = cA[0];
        cuS[r*256 + jc + 1]       = cA[1];
        cuS[(r + 8)*256 + jc]     = cA[2];
        cuS[(r + 8)*256 + jc + 1] = cA[3];
        cuS[r*256 + jc + 8]       = cB[0];
        cuS[r*256 + jc + 9]       = cB[1];
        cuS[(r + 8)*256 + jc + 8] = cB[2];
        cuS[(r + 8)*256 + jc + 9] = cB[3];
    }
    __syncthreads();

    // ---- phase 3: edge GEMM + gelu/W2 epilogue ----
    {
        const uint32_t Abase = smb + A_OFFB;
        for (int task = warp; task < 36; task += 16) {
            int mt = task % 9, nq = task / 9;
            int m0 = mt * 16;
            int r0 = m0 + (lane >> 2);
            int p0 = r0 / 9, p1 = (r0 + 8) / 9;
            uint32_t aaddr = Abase + (m0 + (lane & 15))*ROWB + ((lane >> 4) << 4);
            float acc[4][8];
            #pragma unroll
            for (int nb = 0; nb < 4; ++nb)
                #pragma unroll
                for (int q = 0; q < 8; ++q) acc[nb][q] = 0.0f;
            const uint4* bp = g_Bfrag + (nq*4)*9*32 + lane;
            #pragma unroll
            for (int k = 0; k < 9; ++k) {
                uint32_t af[4];
                ldm_x4(af, aaddr + k*32);
                #pragma unroll
                for (int nb = 0; nb < 4; ++nb) {
                    uint4 bf = bp[(nb*9 + k)*32];
                    mma16816(acc[nb],     af, bf.x, bf.y);
                    mma16816(acc[nb] + 4, af, bf.z, bf.w);
                }
            }
            float part0 = 0.0f, part1 = 0.0f;
            const float* w2q = smf + F_W2 + nq*64;
            #pragma unroll
            for (int nb = 0; nb < 4; ++nb) {
                int jl = nb*16 + (lane & 3)*2;
                int jg = nq*64 + jl;
                const float* cu0 = cuS + p0*256 + jg;
                const float* cu1 = cuS + p1*256 + jg;
                part0 += gelu_exact(acc[nb][0] + cu0[0])*w2q[jl]
                       + gelu_exact(acc[nb][1] + cu0[1])*w2q[jl+1]
                       + gelu_exact(acc[nb][4] + cu0[8])*w2q[jl+8]
                       + gelu_exact(acc[nb][5] + cu0[9])*w2q[jl+9];
                part1 += gelu_exact(acc[nb][2] + cu1[0])*w2q[jl]
                       + gelu_exact(acc[nb][3] + cu1[1])*w2q[jl+1]
                       + gelu_exact(acc[nb][6] + cu1[8])*w2q[jl+8]
                       + gelu_exact(acc[nb][7] + cu1[9])*w2q[jl+9];
            }
            part0 += __shfl_xor_sync(0xffffffffu, part0, 1);
            part0 += __shfl_xor_sync(0xffffffffu, part0, 2);
            part1 += __shfl_xor_sync(0xffffffffu, part1, 1);
            part1 += __shfl_xor_sync(0xffffffffu, part1, 2);
            if ((lane & 3) == 0) {
                smf[F_PART + r0*4 + nq]       = part0;
                smf[F_PART + (r0 + 8)*4 + nq] = part1;
            }
        }
    }
    __syncthreads();

    // ---- phase 4: EML gate ----
    const float gamma = *p_gamma, lam = *p_lam, ebias = *p_bias;
    if (tid < NEDGE) {
        float d = smf[F_PART + tid*4 + 0] + smf[F_PART + tid*4 + 1] + db2[0];
        float r = smf[F_PART + tid*4 + 2] + smf[F_PART + tid*4 + 3] + rb2[0];
        float sp = fmaxf(r, 0.0f) + log1pf(expf(-fabsf(r)));
        float en = gamma * d / (lam * sp + 1e-6f) + ebias;
        en = fminf(fmaxf(en, -3.0f), 3.0f);
        smf[F_GATE + tid] = 1.0f / (1.0f + expf(-en));
    }
    __syncthreads();
    if (tid < TILE_P) {
        float s = 0.0f;
        #pragma unroll
        for (int n = 0; n < 9; ++n) s += smf[F_GATE + tid*9 + n];
        smf[F_SG + tid]   = s;
        smf[F_INVM + tid] = 1.0f / fmaxf(s, 1e-6f);
    }
    __syncthreads();

    // ---- phase 5: ws = (sum_n gate*nbhd)/mass -> bf16 tile (reuse cen tile) ----
    {
        int p = tid >> 5;
        int c0 = lane * 4;
        float im = smf[F_INVM + p];
        float gr[9];
        #pragma unroll
        for (int n = 0; n < 9; ++n) gr[n] = smf[F_GATE + p*9 + n];
        float s0 = 0, s1 = 0, s2 = 0, s3 = 0;
        #pragma unroll
        for (int n = 0; n < 9; ++n) {
            const char* row = smem + A_OFFB + (p*9 + n)*ROWB;
            uint2 u = *(const uint2*)(row + c0*2);
            __nv_bfloat162 lo = *reinterpret_cast<__nv_bfloat162*>(&u.x);
            __nv_bfloat162 hi = *reinterpret_cast<__nv_bfloat162*>(&u.y);
            s0 += gr[n] * __bfloat162float(lo.x);
            s1 += gr[n] * __bfloat162float(lo.y);
            s2 += gr[n] * __bfloat162float(hi.x);
            s3 += gr[n] * __bfloat162float(hi.y);
        }
        __nv_bfloat162 lo2 = __floats2bfloat162_rn(s0*im, s1*im);
        __nv_bfloat162 hi2 = __floats2bfloat162_rn(s2*im, s3*im);
        uint2 st;
        st.x = *reinterpret_cast<uint32_t*>(&lo2);
        st.y = *reinterpret_cast<uint32_t*>(&hi2);
        *(uint2*)(smem + CW_OFFB + p*CROWB + c0*2) = st;
    }
    __syncthreads();

    // ---- phase 6: u GEMM (ws @ Wcomb) + tokens + coef*vbo + ob -> uS f32 ----
    if (warp < 8) {
        uint32_t aaddr = smb + CW_OFFB + (lane & 15)*CROWB + ((lane >> 4) << 4);
        uint32_t af[8][4];
        #pragma unroll
        for (int k = 0; k < 8; ++k) ldm_x4(af[k], aaddr + k*32);
        float cA[4] = {0,0,0,0}, cB[4] = {0,0,0,0};
        const uint4* wp = g_Wfrag + (warp*8)*32 + lane;
        #pragma unroll
        for (int k = 0; k < 8; ++k) {
            uint4 bf = wp[k*32];
            mma16816(cA, af[k], bf.x, bf.y);
            mma16816(cB, af[k], bf.z, bf.w);
        }
        int r = lane >> 2, jc = (lane & 3)*2, j0 = warp*16;
        int p0 = r, p1 = r + 8;
        float coef0 = smf[F_SG + p0] * smf[F_INVM + p0];
        float coef1 = smf[F_SG + p1] * smf[F_INVM + p1];
        int d00 = j0 + jc, d10 = j0 + 8 + jc;
        float2 tA0 = *(const float2*)(tokens + (long)(rowbase + p0)*CC + d00);
        float2 tA1 = *(const float2*)(tokens + (long)(rowbase + p0)*CC + d10);
        float2 tB0 = *(const float2*)(tokens + (long)(rowbase + p1)*CC + d00);
        float2 tB1 = *(const float2*)(tokens + (long)(rowbase + p1)*CC + d10);
        uS[p0*CC + d00]     = cA[0] + tA0.x + coef0*smf[F_VBO + d00]     + smf[F_OB + d00];
        uS[p0*CC + d00 + 1] = cA[1] + tA0.y + coef0*smf[F_VBO + d00 + 1] + smf[F_OB + d00 + 1];
        uS[p1*CC + d00]     = cA[2] + tB0.x + coef1*smf[F_VBO + d00]     + smf[F_OB + d00];
        uS[p1*CC + d00 + 1] = cA[3] + tB0.y + coef1*smf[F_VBO + d00 + 1] + smf[F_OB + d00 + 1];
        uS[p0*CC + d10]     = cB[0] + tA1.x + coef0*smf[F_VBO + d10]     + smf[F_OB + d10];
        uS[p0*CC + d10 + 1] = cB[1] + tA1.y + coef0*smf[F_VBO + d10 + 1] + smf[F_OB + d10 + 1];
        uS[p1*CC + d10]     = cB[2] + tB1.x + coef1*smf[F_VBO + d10]     + smf[F_OB + d10];
        uS[p1*CC + d10 + 1] = cB[3] + tB1.y + coef1*smf[F_VBO + d10 + 1] + smf[F_OB + d10 + 1];
    }
    __syncthreads();

    // ---- phase 7: LN2 + store (warp per position) ----
    {
        int p = warp;
        float4 x = reinterpret_cast<const float4*>(uS + p*CC)[lane];
        float s = x.x + x.y + x.z + x.w;
        #pragma unroll
        for (int o = 16; o; o >>= 1) s += __shfl_xor_sync(0xffffffffu, s, o);
        float m = s * (1.0f/128.0f);
        float dx = x.x - m, dy = x.y - m, dz = x.z - m, dw = x.w - m;
        float v = dx*dx + dy*dy + dz*dz + dw*dw;
        #pragma unroll
        for (int o = 16; o; o >>= 1) v += __shfl_xor_sync(0xffffffffu, v, o);
        float rs = rsqrtf(v * (1.0f/128.0f) + 1e-5f);
        int c = lane * 4;
        float4 o4;
        o4.x = dx*rs*ln2_g[c+0] + ln2_b[c+0];
        o4.y = dy*rs*ln2_g[c+1] + ln2_b[c+1];
        o4.z = dz*rs*ln2_g[c+2] + ln2_b[c+2];
        o4.w = dw*rs*ln2_g[c+3] + ln2_b[c+3];
        reinterpret_cast<float4*>(out + (long)(rowbase + p)*CC)[lane] = o4;
    }
}

// ---------------- launch ----------------
extern "C" void kernel_launch(void* const* d_in, const int* in_sizes, int n_in,
                              void* d_out, int out_size) {
    const float* tokens = (const float*)d_in[0];
    const float* ln1_g  = (const float*)d_in[1];
    const float* ln1_b  = (const float*)d_in[2];
    const float* ln2_g  = (const float*)d_in[3];
    const float* ln2_b  = (const float*)d_in[4];
    const float* rel_pos= (const float*)d_in[5];
    const float* dW1    = (const float*)d_in[6];
    const float* db1    = (const float*)d_in[7];
    const float* dW2    = (const float*)d_in[8];
    const float* db2    = (const float*)d_in[9];
    const float* rW1    = (const float*)d_in[10];
    const float* rb1    = (const float*)d_in[11];
    const float* rW2    = (const float*)d_in[12];
    const float* rb2    = (const float*)d_in[13];
    const float* vW     = (const float*)d_in[14];
    const float* vb     = (const float*)d_in[15];
    const float* oW     = (const float*)d_in[16];
    const float* ob     = (const float*)d_in[17];
    const float* gamma  = (const float*)d_in[18];
    const float* lam    = (const float*)d_in[19];
    const float* ebias  = (const float*)d_in[20];
    float* out = (float*)d_out;

    setup_kernel<<<4162, 256>>>(tokens, ln1_g, ln1_b, vW, oW, vb);
    cudaFuncSetAttribute(bfrag_kernel, cudaFuncAttributeMaxDynamicSharedMemorySize, 256*ROWB);
    bfrag_kernel<<<1, NT, 256*ROWB>>>(dW1, db1, rW1, rb1, rel_pos);
    cudaFuncSetAttribute(eml_main_kernel, cudaFuncAttributeMaxDynamicSharedMemorySize, SMEM_TOTAL);
    eml_main_kernel<<<(BB*HH*WW)/TILE_P, NT, SMEM_TOTAL>>>(tokens, ln2_g, ln2_b, dW2, db2,
                                                           rW2, rb2, ob,
                                                           gamma, lam, ebias, out);
}

// round 13
// speedup vs baseline: 2.8930x; 1.4511x over previous
#include <cuda_runtime.h>
#include <cuda_bf16.h>
#include <cstdint>

#define BB 2
#define HH 128
#define WW 128
#define CC 128
#define NBR 9
#define TILE_P 16
#define NEDGE 144
#define NT 512

#define KP 152                 /* padded edge-A cols */
#define ROWB (KP*2)            /* 304 B rows (conflict-free ldmatrix) */
#define CROWB 272              /* cen/ws tile row stride bytes */

// ---- smem float indices (misc block = 3008 floats = 12032 B) ----
#define F_PART  0       /* [144][16] per-(edge, n16) partials */
#define F_GATE  2304
#define F_SG    2448
#define F_INVM  2464
#define F_W2    2496    /* [256]: dW2 | rW2 */
#define F_VBO   2752    /* [128] vb@oW */
#define F_OB    2880    /* [128] ob */
// ---- smem byte offsets (main kernel) ----
#define CU_OFFB   12032
#define CW_OFFB   (CU_OFFB + 16384)           // 28416
#define A_OFFB    (CW_OFFB + 4352)            // 32768
#define SMEM_TOTAL (A_OFFB + 43776)           // 76544
#define SETUP_SMEM 77824                      // 256*ROWB staging

// ---- device scratch ----
__device__ float g_norm[BB*HH*WW*CC];
__device__ float g_vbo[CC];
__device__ uint32_t g_map[1152];
__device__ uint4 g_Bfrag[16*9*32];           // edge B fragments [n16][k][lane]
__device__ uint4 g_Ufrag[16*8*32];           // U fragments
__device__ uint4 g_Wfrag[8*8*32];            // Wcomb fragments

// ---- helpers ----
__device__ __forceinline__ float gelu_exact(float x) {
    return 0.5f * x * (1.0f + erff(x * 0.70710678118654752f));
}
__device__ __forceinline__ uint32_t smem_u32(const void* p) {
    uint32_t a;
    asm("{ .reg .u64 t; cvta.to.shared.u64 t, %1; cvt.u32.u64 %0, t; }" : "=r"(a) : "l"(p));
    return a;
}
__device__ __forceinline__ void ldm_x4(uint32_t* r, uint32_t addr) {
    asm volatile("ldmatrix.sync.aligned.m8n8.x4.shared.b16 {%0,%1,%2,%3}, [%4];"
        : "=r"(r[0]), "=r"(r[1]), "=r"(r[2]), "=r"(r[3]) : "r"(addr));
}
__device__ __forceinline__ void mma16816(float* c, const uint32_t* a, uint32_t b0, uint32_t b1) {
    asm volatile("mma.sync.aligned.m16n8k16.row.col.f32.bf16.bf16.f32 "
        "{%0,%1,%2,%3}, {%4,%5,%6,%7}, {%8,%9}, {%0,%1,%2,%3};"
        : "+f"(c[0]), "+f"(c[1]), "+f"(c[2]), "+f"(c[3])
        : "r"(a[0]), "r"(a[1]), "r"(a[2]), "r"(a[3]), "r"(b0), "r"(b1));
}

__device__ __forceinline__ float b_val(int j, int c,
        const float* dW1, const float* db1, const float* rW1, const float* rb1,
        const float* rel_pos) {
    float val = 0.0f;
    if (c < 128) {
        val = (j < 128) ? dW1[(128 + c)*CC + j]       - dW1[(256 + c)*CC + j]
                        : rW1[(128 + c)*CC + (j-128)] - rW1[(256 + c)*CC + (j-128)];
    } else if (c < 137) {
        int n = c - 128;
        if (j < 128) {
            float bd = db1[j];
            #pragma unroll
            for (int r = 0; r < 8; ++r) bd += rel_pos[n*8 + r] * dW1[(384 + r)*CC + j];
            val = bd;
        } else {
            float br = rb1[j - 128];
            #pragma unroll
            for (int r = 0; r < 8; ++r) br += rel_pos[n*8 + r] * rW1[(384 + r)*CC + (j-128)];
            val = br;
        }
    }
    return val;
}

// ================= setup: LN1 (blocks 0..2047) + frag builders (2048..2051) =================
__global__ void setup_kernel(const float* __restrict__ tokens,
                             const float* __restrict__ g, const float* __restrict__ b,
                             const float* __restrict__ dW1, const float* __restrict__ db1,
                             const float* __restrict__ rW1, const float* __restrict__ rb1,
                             const float* __restrict__ rel_pos,
                             const float* __restrict__ vW, const float* __restrict__ oW,
                             const float* __restrict__ vb) {
    extern __shared__ char s[];
    const int tid = threadIdx.x;
    const int warp = tid >> 5, lane = tid & 31;
    const uint32_t sb = smem_u32(s);

    if (blockIdx.x < 2048) {
        // --- LN1: 16 rows per block (512 threads) ---
        int row = blockIdx.x * 16 + warp;
        float4 x = reinterpret_cast<const float4*>(tokens + (long)row*CC)[lane];
        float su = x.x + x.y + x.z + x.w;
        #pragma unroll
        for (int o = 16; o; o >>= 1) su += __shfl_xor_sync(0xffffffffu, su, o);
        float m = su * (1.0f/128.0f);
        float dx = x.x - m, dy = x.y - m, dz = x.z - m, dw = x.w - m;
        float v = dx*dx + dy*dy + dz*dz + dw*dw;
        #pragma unroll
        for (int o = 16; o; o >>= 1) v += __shfl_xor_sync(0xffffffffu, v, o);
        float rs = rsqrtf(v * (1.0f/128.0f) + 1e-5f);
        int c = lane * 4;
        float4 o4;
        o4.x = dx*rs*g[c+0] + b[c+0];
        o4.y = dy*rs*g[c+1] + b[c+1];
        o4.z = dz*rs*g[c+2] + b[c+2];
        o4.w = dw*rs*g[c+3] + b[c+3];
        reinterpret_cast<float4*>(g_norm + (long)row*CC)[lane] = o4;
    } else if (blockIdx.x == 2048) {
        // --- edge B fragments ---
        for (int idx = tid; idx < 256*KP; idx += NT) {
            int j = idx / KP, c = idx - (idx / KP)*KP;
            *(__nv_bfloat16*)(s + j*ROWB + c*2) =
                __float2bfloat16(b_val(j, c, dW1, db1, rW1, rb1, rel_pos));
        }
        __syncthreads();
        int n0 = warp * 16;
        uint32_t baddr = sb + (uint32_t)((n0 + (lane & 7) + ((lane >> 4) << 3))*ROWB
                       + (((lane >> 3) & 1) << 4));
        #pragma unroll
        for (int k = 0; k < 9; ++k) {
            uint32_t bf[4];
            ldm_x4(bf, baddr + k*32);
            g_Bfrag[(warp*9 + k)*32 + lane] = make_uint4(bf[0], bf[1], bf[2], bf[3]);
        }
    } else if (blockIdx.x == 2049) {
        // --- U fragments ---
        for (int idx = tid; idx < 256*128; idx += NT) {
            int j = idx >> 7, c = idx & 127;
            float val = (j < 128) ? dW1[c*CC + j]       + dW1[(256 + c)*CC + j]
                                  : rW1[c*CC + (j-128)] + rW1[(256 + c)*CC + (j-128)];
            *(__nv_bfloat16*)(s + j*CROWB + c*2) = __float2bfloat16(val);
        }
        __syncthreads();
        int n0 = warp * 16;
        uint32_t baddr = sb + (uint32_t)((n0 + (lane & 7) + ((lane >> 4) << 3))*CROWB
                       + (((lane >> 3) & 1) << 4));
        #pragma unroll
        for (int k = 0; k < 8; ++k) {
            uint32_t bf[4];
            ldm_x4(bf, baddr + k*32);
            g_Ufrag[(warp*8 + k)*32 + lane] = make_uint4(bf[0], bf[1], bf[2], bf[3]);
        }
    } else if (blockIdx.x == 2050) {
        // --- Wcomb fragments + vbo ---
        for (int idx = tid; idx < 128*128; idx += NT) {
            int c = idx >> 7, j = idx & 127;
            float su = 0.0f;
            #pragma unroll 4
            for (int e = 0; e < 128; ++e) su = fmaf(vW[c*CC + e], oW[e*CC + j], su);
            *(__nv_bfloat16*)(s + j*CROWB + c*2) = __float2bfloat16(su);
        }
        if (tid < 128) {
            float su = 0.0f;
            #pragma unroll 4
            for (int e = 0; e < 128; ++e) su = fmaf(vb[e], oW[e*CC + tid], su);
            g_vbo[tid] = su;
        }
        __syncthreads();
        if (warp < 8) {
            int n0 = warp * 16;
            uint32_t baddr = sb + (uint32_t)((n0 + (lane & 7) + ((lane >> 4) << 3))*CROWB
                           + (((lane >> 3) & 1) << 4));
            #pragma unroll
            for (int k = 0; k < 8; ++k) {
                uint32_t bf[4];
                ldm_x4(bf, baddr + k*32);
                g_Wfrag[(warp*8 + k)*32 + lane] = make_uint4(bf[0], bf[1], bf[2], bf[3]);
            }
        }
    } else {
        // --- gather map ---
        for (int r0 = tid; r0 < 1152; r0 += NT) {
            int sft = r0 >> 7;
            int c2  = r0 & 127;
            int f   = c2*9 + sft;
            int n   = f >> 7;
            int c   = f & 127;
            int di  = sft / 3;
            int dj  = sft - di*3;
            uint32_t dst = (uint32_t)(n*ROWB + c*2);
            g_map[r0] = (dst << 11) | ((uint32_t)di << 9) | ((uint32_t)dj << 7) | (uint32_t)c2;
        }
    }
}

// ================= main fused kernel: CTA = 16 positions =================
__global__ __launch_bounds__(NT, 2)
void eml_main_kernel(const float* __restrict__ tokens,
                     const float* __restrict__ ln2_g, const float* __restrict__ ln2_b,
                     const float* __restrict__ dW2, const float* __restrict__ db2,
                     const float* __restrict__ rW2, const float* __restrict__ rb2,
                     const float* __restrict__ ob,
                     const float* __restrict__ p_gamma, const float* __restrict__ p_lam,
                     const float* __restrict__ p_bias,
                     float* __restrict__ out) {
    extern __shared__ char smem[];
    float* smf = (float*)smem;
    float* cuS = (float*)(smem + CU_OFFB);        // [16][256]
    float* uS  = (float*)(smem + A_OFFB);         // aliases edge A (dead by then)
    const uint32_t smb = smem_u32(smem);

    const int tid  = threadIdx.x;
    const int warp = tid >> 5, lane = tid & 31;
    const int blk = blockIdx.x;
    const int b   = blk >> 10;
    const int t   = blk & 1023;
    const int h   = t >> 3;
    const int w0  = (t & 7) << 4;
    const int rowbase = (b*HH + h)*WW + w0;

    // ---- phase 0: ext-col zero + one-hot; cen bf16 stage; w2/vbo/ob ----
    if (tid < NEDGE) {
        char* row = smem + A_OFFB + tid*ROWB;
        uint4 z = make_uint4(0, 0, 0, 0);
        *(uint4*)(row + 256) = z;
        *(uint4*)(row + 272) = z;
        *(uint4*)(row + 288) = z;
        int n = tid - (tid / 9)*9;
        *(__nv_bfloat16*)(row + (128 + n)*2) = __float2bfloat16(1.0f);
    }
    for (int i = tid; i < 1024; i += NT) {
        int p = i >> 6, cp = i & 63;
        float2 v = *(const float2*)(g_norm + (long)(rowbase + p)*CC + cp*2);
        *(__nv_bfloat162*)(smem + CW_OFFB + p*CROWB + cp*4) = __floats2bfloat162_rn(v.x, v.y);
    }
    if (tid < 256)      smf[F_W2 + tid] = (tid < 128) ? dW2[tid] : rW2[tid - 128];
    else if (tid < 384) smf[F_VBO + tid - 256] = g_vbo[tid - 256];
    else                smf[F_OB + tid - 384]  = ob[tid - 384];

    // ---- phase 1: map-based gather -> edge A bf16 ----
    for (int r0 = tid; r0 < 1152; r0 += NT) {
        uint32_t pk = g_map[r0];
        int c2 = pk & 127;
        int dj = (pk >> 7) & 3;
        int di = (pk >> 9) & 3;
        uint32_t dst = pk >> 11;
        int hh = h + di - 1;
        bool hok = (unsigned)hh < HH;
        long srow = (long)(b*HH + hh)*WW;
        char* dbase = smem + A_OFFB + dst;
        #pragma unroll
        for (int p = 0; p < 16; ++p) {
            int ww = w0 + p + dj - 1;
            float val = 0.0f;
            if (hok && (unsigned)ww < WW) val = g_norm[(srow + ww)*CC + c2];
            *(__nv_bfloat16*)(dbase + p*(9*ROWB)) = __float2bfloat16(val);
        }
    }
    __syncthreads();

    // ---- phase 2: cu GEMM (cen @ U) ----
    {
        uint32_t aaddr = smb + CW_OFFB + (lane & 15)*CROWB + ((lane >> 4) << 4);
        uint32_t af[8][4];
        #pragma unroll
        for (int k = 0; k < 8; ++k) ldm_x4(af[k], aaddr + k*32);
        float cA[4] = {0,0,0,0}, cB[4] = {0,0,0,0};
        const uint4* up = g_Ufrag + (warp*8)*32 + lane;
        #pragma unroll
        for (int k = 0; k < 8; ++k) {
            uint4 bf = up[k*32];
            mma16816(cA, af[k], bf.x, bf.y);
            mma16816(cB, af[k], bf.z, bf.w);
        }
        int r = lane >> 2, jc = warp*16 + (lane & 3)*2;
        cuS[r*256 + jc]           = cA[0];
        cuS[r*256 + jc + 1]       = cA[1];
        cuS[(r + 8)*256 + jc]     = cA[2];
        cuS[(r + 8)*256 + jc + 1] = cA[3];
        cuS[r*256 + jc + 8]       = cB[0];
        cuS[r*256 + jc + 9]       = cB[1];
        cuS[(r + 8)*256 + jc + 8] = cB[2];
        cuS[(r + 8)*256 + jc + 9] = cB[3];
    }
    __syncthreads();

    // ---- phase 3: edge GEMM, warp = n16 block (even 9 m-tiles each) ----
    {
        const uint32_t Abase = smb + A_OFFB;
        const int ni = warp;                          // n16 block 0..15
        const uint4* bp = g_Bfrag + (ni*9)*32 + lane;
        const int jgg = ni*16 + (lane & 3)*2;         // global j of acc[0]
        const float w20 = smf[F_W2 + jgg],     w21 = smf[F_W2 + jgg + 1];
        const float w28 = smf[F_W2 + jgg + 8], w29 = smf[F_W2 + jgg + 9];
        #pragma unroll
        for (int mt = 0; mt < 9; ++mt) {
            int m0 = mt * 16;
            int r0 = m0 + (lane >> 2);
            int p0 = r0 / 9, p1 = (r0 + 8) / 9;
            uint32_t aaddr = Abase + (m0 + (lane & 15))*ROWB + ((lane >> 4) << 4);
            float acc[8];
            #pragma unroll
            for (int q = 0; q < 8; ++q) acc[q] = 0.0f;
            #pragma unroll
            for (int k = 0; k < 9; ++k) {
                uint32_t af[4];
                ldm_x4(af, aaddr + k*32);
                uint4 bf = bp[k*32];
                mma16816(acc,     af, bf.x, bf.y);
                mma16816(acc + 4, af, bf.z, bf.w);
            }
            const float* cu0 = cuS + p0*256 + jgg;
            const float* cu1 = cuS + p1*256 + jgg;
            float part0 = gelu_exact(acc[0] + cu0[0])*w20 + gelu_exact(acc[1] + cu0[1])*w21
                        + gelu_exact(acc[4] + cu0[8])*w28 + gelu_exact(acc[5] + cu0[9])*w29;
            float part1 = gelu_exact(acc[2] + cu1[0])*w20 + gelu_exact(acc[3] + cu1[1])*w21
                        + gelu_exact(acc[6] + cu1[8])*w28 + gelu_exact(acc[7] + cu1[9])*w29;
            part0 += __shfl_xor_sync(0xffffffffu, part0, 1);
            part0 += __shfl_xor_sync(0xffffffffu, part0, 2);
            part1 += __shfl_xor_sync(0xffffffffu, part1, 1);
            part1 += __shfl_xor_sync(0xffffffffu, part1, 2);
            if ((lane & 3) == 0) {
                smf[F_PART + r0*16 + ni]       = part0;
                smf[F_PART + (r0 + 8)*16 + ni] = part1;
            }
        }
    }
    __syncthreads();

    // ---- phase 4: EML gate ----
    const float gamma = *p_gamma, lam = *p_lam, ebias = *p_bias;
    if (tid < NEDGE) {
        const float4* pr = (const float4*)(smf + F_PART + tid*16);
        float4 a = pr[0], b4 = pr[1], c4 = pr[2], e4 = pr[3];
        float d = a.x + a.y + a.z + a.w + b4.x + b4.y + b4.z + b4.w + db2[0];
        float r = c4.x + c4.y + c4.z + c4.w + e4.x + e4.y + e4.z + e4.w + rb2[0];
        float sp = fmaxf(r, 0.0f) + log1pf(expf(-fabsf(r)));
        float en = gamma * d / (lam * sp + 1e-6f) + ebias;
        en = fminf(fmaxf(en, -3.0f), 3.0f);
        smf[F_GATE + tid] = 1.0f / (1.0f + expf(-en));
    }
    __syncthreads();
    if (tid < TILE_P) {
        float s = 0.0f;
        #pragma unroll
        for (int n = 0; n < 9; ++n) s += smf[F_GATE + tid*9 + n];
        smf[F_SG + tid]   = s;
        smf[F_INVM + tid] = 1.0f / fmaxf(s, 1e-6f);
    }
    __syncthreads();

    // ---- phase 5: ws = (sum_n gate*nbhd)/mass -> bf16 tile ----
    {
        int p = tid >> 5;
        int c0 = lane * 4;
        float im = smf[F_INVM + p];
        float gr[9];
        #pragma unroll
        for (int n = 0; n < 9; ++n) gr[n] = smf[F_GATE + p*9 + n];
        float s0 = 0, s1 = 0, s2 = 0, s3 = 0;
        #pragma unroll
        for (int n = 0; n < 9; ++n) {
            const char* row = smem + A_OFFB + (p*9 + n)*ROWB;
            uint2 u = *(const uint2*)(row + c0*2);
            __nv_bfloat162 lo = *reinterpret_cast<__nv_bfloat162*>(&u.x);
            __nv_bfloat162 hi = *reinterpret_cast<__nv_bfloat162*>(&u.y);
            s0 += gr[n] * __bfloat162float(lo.x);
            s1 += gr[n] * __bfloat162float(lo.y);
            s2 += gr[n] * __bfloat162float(hi.x);
            s3 += gr[n] * __bfloat162float(hi.y);
        }
        __nv_bfloat162 lo2 = __floats2bfloat162_rn(s0*im, s1*im);
        __nv_bfloat162 hi2 = __floats2bfloat162_rn(s2*im, s3*im);
        uint2 st;
        st.x = *reinterpret_cast<uint32_t*>(&lo2);
        st.y = *reinterpret_cast<uint32_t*>(&hi2);
        *(uint2*)(smem + CW_OFFB + p*CROWB + c0*2) = st;
    }
    __syncthreads();

    // ---- phase 6: u GEMM (ws @ Wcomb) + tokens + coef*vbo + ob -> uS f32 ----
    if (warp < 8) {
        uint32_t aaddr = smb + CW_OFFB + (lane & 15)*CROWB + ((lane >> 4) << 4);
        uint32_t af[8][4];
        #pragma unroll
        for (int k = 0; k < 8; ++k) ldm_x4(af[k], aaddr + k*32);
        float cA[4] = {0,0,0,0}, cB[4] = {0,0,0,0};
        const uint4* wp = g_Wfrag + (warp*8)*32 + lane;
        #pragma unroll
        for (int k = 0; k < 8; ++k) {
            uint4 bf = wp[k*32];
            mma16816(cA, af[k], bf.x, bf.y);
            mma16816(cB, af[k], bf.z, bf.w);
        }
        int r = lane >> 2, jc = (lane & 3)*2, j0 = warp*16;
        int p0 = r, p1 = r + 8;
        float coef0 = smf[F_SG + p0] * smf[F_INVM + p0];
        float coef1 = smf[F_SG + p1] * smf[F_INVM + p1];
        int d00 = j0 + jc, d10 = j0 + 8 + jc;
        float2 tA0 = *(const float2*)(tokens + (long)(rowbase + p0)*CC + d00);
        float2 tA1 = *(const float2*)(tokens + (long)(rowbase + p0)*CC + d10);
        float2 tB0 = *(const float2*)(tokens + (long)(rowbase + p1)*CC + d00);
        float2 tB1 = *(const float2*)(tokens + (long)(rowbase + p1)*CC + d10);
        uS[p0*CC + d00]     = cA[0] + tA0.x + coef0*smf[F_VBO + d00]     + smf[F_OB + d00];
        uS[p0*CC + d00 + 1] = cA[1] + tA0.y + coef0*smf[F_VBO + d00 + 1] + smf[F_OB + d00 + 1];
        uS[p1*CC + d00]     = cA[2] + tB0.x + coef1*smf[F_VBO + d00]     + smf[F_OB + d00];
        uS[p1*CC + d00 + 1] = cA[3] + tB0.y + coef1*smf[F_VBO + d00 + 1] + smf[F_OB + d00 + 1];
        uS[p0*CC + d10]     = cB[0] + tA1.x + coef0*smf[F_VBO + d10]     + smf[F_OB + d10];
        uS[p0*CC + d10 + 1] = cB[1] + tA1.y + coef0*smf[F_VBO + d10 + 1] + smf[F_OB + d10 + 1];
        uS[p1*CC + d10]     = cB[2] + tB1.x + coef1*smf[F_VBO + d10]     + smf[F_OB + d10];
        uS[p1*CC + d10 + 1] = cB[3] + tB1.y + coef1*smf[F_VBO + d10 + 1] + smf[F_OB + d10 + 1];
    }
    __syncthreads();

    // ---- phase 7: LN2 + store (warp per position) ----
    {
        int p = warp;
        float4 x = reinterpret_cast<const float4*>(uS + p*CC)[lane];
        float s = x.x + x.y + x.z + x.w;
        #pragma unroll
        for (int o = 16; o; o >>= 1) s += __shfl_xor_sync(0xffffffffu, s, o);
        float m = s * (1.0f/128.0f);
        float dx = x.x - m, dy = x.y - m, dz = x.z - m, dw = x.w - m;
        float v = dx*dx + dy*dy + dz*dz + dw*dw;
        #pragma unroll
        for (int o = 16; o; o >>= 1) v += __shfl_xor_sync(0xffffffffu, v, o);
        float rs = rsqrtf(v * (1.0f/128.0f) + 1e-5f);
        int c = lane * 4;
        float4 o4;
        o4.x = dx*rs*ln2_g[c+0] + ln2_b[c+0];
        o4.y = dy*rs*ln2_g[c+1] + ln2_b[c+1];
        o4.z = dz*rs*ln2_g[c+2] + ln2_b[c+2];
        o4.w = dw*rs*ln2_g[c+3] + ln2_b[c+3];
        reinterpret_cast<float4*>(out + (long)(rowbase + p)*CC)[lane] = o4;
    }
}

// ---------------- launch ----------------
extern "C" void kernel_launch(void* const* d_in, const int* in_sizes, int n_in,
                              void* d_out, int out_size) {
    const float* tokens = (const float*)d_in[0];
    const float* ln1_g  = (const float*)d_in[1];
    const float* ln1_b  = (const float*)d_in[2];
    const float* ln2_g  = (const float*)d_in[3];
    const float* ln2_b  = (const float*)d_in[4];
    const float* rel_pos= (const float*)d_in[5];
    const float* dW1    = (const float*)d_in[6];
    const float* db1    = (const float*)d_in[7];
    const float* dW2    = (const float*)d_in[8];
    const float* db2    = (const float*)d_in[9];
    const float* rW1    = (const float*)d_in[10];
    const float* rb1    = (const float*)d_in[11];
    const float* rW2    = (const float*)d_in[12];
    const float* rb2    = (const float*)d_in[13];
    const float* vW     = (const float*)d_in[14];
    const float* vb     = (const float*)d_in[15];
    const float* oW     = (const float*)d_in[16];
    const float* ob     = (const float*)d_in[17];
    const float* gamma  = (const float*)d_in[18];
    const float* lam    = (const float*)d_in[19];
    const float* ebias  = (const float*)d_in[20];
    float* out = (float*)d_out;

    cudaFuncSetAttribute(setup_kernel, cudaFuncAttributeMaxDynamicSharedMemorySize, SETUP_SMEM);
    setup_kernel<<<2052, NT, SETUP_SMEM>>>(tokens, ln1_g, ln1_b, dW1, db1, rW1, rb1,
                                           rel_pos, vW, oW, vb);
    cudaFuncSetAttribute(eml_main_kernel, cudaFuncAttributeMaxDynamicSharedMemorySize, SMEM_TOTAL);
    eml_main_kernel<<<(BB*HH*WW)/TILE_P, NT, SMEM_TOTAL>>>(tokens, ln2_g, ln2_b, dW2, db2,
                                                           rW2, rb2, ob,
                                                           gamma, lam, ebias, out);
}